// round 2
// baseline (speedup 1.0000x reference)
#include <cuda_runtime.h>

#define Dm 1024
#define Nn 64
#define Ne 1024

// ---------------- scratch (device globals; no allocations allowed) ----------------
__device__ float g_vctx[Nn * Dm];
__device__ float g_Xv[Nn * 4 * Dm];
__device__ float g_vj[Nn * Dm];
__device__ float g_S[Nn * Dm];
__device__ float g_O[Nn * Dm];
__device__ float g_Qs[Nn * Dm];
__device__ float g_Qo[Nn * Dm];
__device__ float g_relctx[Ne * Dm];
__device__ float g_Xr[Ne * 4 * Dm];
__device__ float g_rj[Ne * Dm];
__device__ float g_relj[Ne * Dm];
__device__ float g_r2s[Ne * Dm];
__device__ float g_r2o[Ne * Dm];
__device__ float g_Xrc[Ne * 2 * Dm];
__device__ float g_Xc[Nn * 3 * Dm];
__device__ float g_Xn[Nn * 2 * Dm];
__device__ float g_part[16 * Nn * Dm];
__device__ float g_ssbj[Ne];
__device__ float g_sobj[Ne];
__device__ float g_wsbj[Ne];
__device__ float g_wobj[Ne];
__device__ float g_ctxs[Nn * Dm];
__device__ float g_ctxo[Nn * Dm];
__device__ int g_src[Ne];
__device__ int g_dst[Ne];

// ---------------- setup ----------------
__global__ void k_setup(const float* __restrict__ v, const float* __restrict__ rel,
                        const int* __restrict__ eidx) {
    int i0 = blockIdx.x * blockDim.x + threadIdx.x;
    int stride = gridDim.x * blockDim.x;
    for (int t = i0; t < Ne * Dm; t += stride) g_relctx[t] = rel[t];
    for (int t = i0; t < Nn * Dm; t += stride) g_vctx[t] = v[t];
    for (int t = i0; t < Ne; t += stride) {
        int e = eidx[t];
        g_src[t] = e >> 6;
        g_dst[t] = e & 63;
    }
}

// ---------------- concat builders ----------------
__global__ void k_build_Xv(const float* __restrict__ v) {
    int idx = blockIdx.x * blockDim.x + threadIdx.x;
    if (idx >= Nn * Dm) return;
    int i = idx >> 10, d = idx & 1023;
    float a = v[idx], c = g_vctx[idx];
    float* row = g_Xv + (size_t)i * 4096;
    row[d] = a; row[1024 + d] = c; row[2048 + d] = a * c; row[3072 + d] = c - a;
}

__global__ void k_build_Xr(const float* __restrict__ rel) {
    int idx = blockIdx.x * blockDim.x + threadIdx.x;
    if (idx >= Ne * Dm) return;
    int e = idx >> 10, d = idx & 1023;
    float r = rel[idx], c = g_relctx[idx];
    float* row = g_Xr + (size_t)e * 4096;
    row[d] = r; row[1024 + d] = c; row[2048 + d] = r * c; row[3072 + d] = r - c;
}

__global__ void k_build_Xrc() {
    int idx = blockIdx.x * blockDim.x + threadIdx.x;
    if (idx >= Ne * Dm) return;
    int e = idx >> 10, d = idx & 1023;
    float* row = g_Xrc + (size_t)e * 2048;
    row[d] = g_relctx[idx]; row[1024 + d] = g_relj[idx];
}

__global__ void k_build_Xc() {
    int idx = blockIdx.x * blockDim.x + threadIdx.x;
    if (idx >= Nn * Dm) return;
    int i = idx >> 10, d = idx & 1023;
    float* row = g_Xc + (size_t)i * 3072;
    row[d] = g_vctx[idx]; row[1024 + d] = g_ctxs[idx]; row[2048 + d] = g_ctxo[idx];
}

__global__ void k_build_Xout(const float* __restrict__ rel) {
    int idx = blockIdx.x * blockDim.x + threadIdx.x;
    if (idx >= Ne * Dm) return;
    int e = idx >> 10, d = idx & 1023;
    float* row = g_Xrc + (size_t)e * 2048;
    row[d] = rel[idx]; row[1024 + d] = g_relctx[idx];
}

__global__ void k_build_Xn(const float* __restrict__ v) {
    int idx = blockIdx.x * blockDim.x + threadIdx.x;
    if (idx >= Nn * Dm) return;
    int i = idx >> 10, d = idx & 1023;
    float* row = g_Xn + (size_t)i * 2048;
    row[d] = v[idx]; row[1024 + d] = g_vctx[idx];
}

// ---------------- generic NT GEMM: C[M,1024] = A[M,K] * B[1024,K]^T ----------------
// tiles: BM=64, BN=128, BK=16; 128 threads; 8x8 microtile.
// MODE 0: plain.  MODE 1: += g_S[src[m]] + g_O[dst[m]] (rel_j epilogue).
// grid = (8, M/64, splitk); Kc = K/splitk; split writes C + z*strideCz.
template <int MODE>
__global__ void __launch_bounds__(128) k_gemm(
    const float* __restrict__ A, int lda,
    const float* __restrict__ B, int ldb,
    float* __restrict__ C, size_t strideCz, int Kc) {
    __shared__ float As[16][64];
    __shared__ float Bs[16][128];
    int tid = threadIdx.x;
    int trow = tid >> 4;   // 0..7
    int tcol = tid & 15;   // 0..15
    const float* Ab = A + (size_t)blockIdx.y * 64 * lda + (size_t)blockIdx.z * Kc;
    const float* Bb = B + (size_t)blockIdx.x * 128 * ldb + (size_t)blockIdx.z * Kc;

    float acc[8][8];
#pragma unroll
    for (int i = 0; i < 8; ++i)
#pragma unroll
        for (int j = 0; j < 8; ++j) acc[i][j] = 0.f;

    for (int k0 = 0; k0 < Kc; k0 += 16) {
#pragma unroll
        for (int it = 0; it < 2; ++it) {
            int f = tid + it * 128;
            int r = f >> 2, q = f & 3;
            float4 vv = *(const float4*)(Ab + (size_t)r * lda + k0 + q * 4);
            As[q * 4 + 0][r] = vv.x; As[q * 4 + 1][r] = vv.y;
            As[q * 4 + 2][r] = vv.z; As[q * 4 + 3][r] = vv.w;
        }
#pragma unroll
        for (int it = 0; it < 4; ++it) {
            int f = tid + it * 128;
            int r = f >> 2, q = f & 3;
            float4 vv = *(const float4*)(Bb + (size_t)r * ldb + k0 + q * 4);
            Bs[q * 4 + 0][r] = vv.x; Bs[q * 4 + 1][r] = vv.y;
            Bs[q * 4 + 2][r] = vv.z; Bs[q * 4 + 3][r] = vv.w;
        }
        __syncthreads();
#pragma unroll
        for (int kk = 0; kk < 16; ++kk) {
            float a[8], b[8];
            *(float4*)(a)     = *(const float4*)&As[kk][trow * 8];
            *(float4*)(a + 4) = *(const float4*)&As[kk][trow * 8 + 4];
            *(float4*)(b)     = *(const float4*)&Bs[kk][tcol * 8];
            *(float4*)(b + 4) = *(const float4*)&Bs[kk][tcol * 8 + 4];
#pragma unroll
            for (int i = 0; i < 8; ++i)
#pragma unroll
                for (int j = 0; j < 8; ++j) acc[i][j] += a[i] * b[j];
        }
        __syncthreads();
    }

    float* Cz = C + (size_t)blockIdx.z * strideCz;
    int m0 = blockIdx.y * 64 + trow * 8;
    int n0 = blockIdx.x * 128 + tcol * 8;
#pragma unroll
    for (int i = 0; i < 8; ++i) {
        int m = m0 + i;
        float* crow = Cz + (size_t)m * 1024 + n0;
        float o[8];
        if (MODE == 1) {
            const float* sp = g_S + (size_t)g_src[m] * 1024 + n0;
            const float* op = g_O + (size_t)g_dst[m] * 1024 + n0;
#pragma unroll
            for (int j = 0; j < 8; ++j) o[j] = acc[i][j] + sp[j] + op[j];
        } else {
#pragma unroll
            for (int j = 0; j < 8; ++j) o[j] = acc[i][j];
        }
        *(float4*)(crow)     = make_float4(o[0], o[1], o[2], o[3]);
        *(float4*)(crow + 4) = make_float4(o[4], o[5], o[6], o[7]);
    }
}

// deterministic split-K reduction (fixed order), optional bias[n] (n = idx % 1024)
__global__ void k_reduce(const float* __restrict__ part, float* __restrict__ C,
                         int total, int splitk, const float* __restrict__ bias) {
    int idx = blockIdx.x * 256 + threadIdx.x;
    if (idx >= total) return;
    float s = 0.f;
    for (int z = 0; z < splitk; ++z) s += part[(size_t)z * total + idx];
    if (bias) s += bias[idx & 1023];
    C[idx] = s;
}

// ---------------- per-edge attention scores ----------------
__global__ void k_score() {
    int e = blockIdx.x;
    int tid = threadIdx.x;  // 128
    int s = g_src[e], o = g_dst[e];
    const float* qs = g_Qs + (size_t)s * Dm;
    const float* qo = g_Qo + (size_t)o * Dm;
    const float* rs = g_r2s + (size_t)e * Dm;
    const float* ro = g_r2o + (size_t)e * Dm;
    float a1 = 0.f, a2 = 0.f;
    for (int d = tid; d < Dm; d += 128) {
        a1 += qs[d] * rs[d];
        a2 += qo[d] * ro[d];
    }
#pragma unroll
    for (int off = 16; off; off >>= 1) {
        a1 += __shfl_down_sync(0xffffffffu, a1, off);
        a2 += __shfl_down_sync(0xffffffffu, a2, off);
    }
    __shared__ float sh1[4], sh2[4];
    if ((tid & 31) == 0) { sh1[tid >> 5] = a1; sh2[tid >> 5] = a2; }
    __syncthreads();
    if (tid == 0) {
        float t1 = sh1[0] + sh1[1] + sh1[2] + sh1[3];
        float t2 = sh2[0] + sh2[1] + sh2[2] + sh2[3];
        g_ssbj[e] = t1 * (1.f / 32.f);
        g_sobj[e] = t2 * (1.f / 32.f);
    }
}

// ---------------- masked softmax over rows (sbj) and cols (obj) ----------------
__global__ void k_softmax(const int* __restrict__ conn) {
    int tid = threadIdx.x;  // 128
    float ex[64];
    if (tid < 64) {
        int i = tid;
        float m = -1e30f;
        for (int j = 0; j < 64; ++j) {
            int k = conn[i * 64 + j];
            if (k >= 0) m = fmaxf(m, g_ssbj[k]);
        }
        float sum = 0.f;
        for (int j = 0; j < 64; ++j) {
            int k = conn[i * 64 + j];
            float e = (k >= 0) ? expf(g_ssbj[k] - m) : 0.f;
            ex[j] = e; sum += e;
        }
        float inv = 1.f / sum;
        for (int j = 0; j < 64; ++j) {
            int k = conn[i * 64 + j];
            if (k >= 0) g_wsbj[k] = ex[j] * inv;
        }
    } else {
        int j = tid - 64;
        float m = -1e30f;
        for (int i = 0; i < 64; ++i) {
            int k = conn[i * 64 + j];
            if (k >= 0) m = fmaxf(m, g_sobj[k]);
        }
        float sum = 0.f;
        for (int i = 0; i < 64; ++i) {
            int k = conn[i * 64 + j];
            float e = (k >= 0) ? expf(g_sobj[k] - m) : 0.f;
            ex[i] = e; sum += e;
        }
        float inv = 1.f / sum;
        for (int i = 0; i < 64; ++i) {
            int k = conn[i * 64 + j];
            if (k >= 0) g_wobj[k] = ex[i] * inv;
        }
    }
}

// ---------------- ctx aggregation (deterministic, atomic-free) ----------------
__global__ void k_ctx(const int* __restrict__ conn) {
    int tid = threadIdx.x;  // 256
    if (blockIdx.y == 0) {
        int i = blockIdx.x;
#pragma unroll
        for (int dd = 0; dd < 4; ++dd) {
            int d = tid + dd * 256;
            float acc = 0.f;
            for (int j = 0; j < 64; ++j) {
                int k = conn[i * 64 + j];
                if (k >= 0) acc += g_wsbj[k] * g_relj[(size_t)k * Dm + d];
            }
            g_ctxs[(size_t)i * Dm + d] = acc;
        }
    } else {
        int j = blockIdx.x;
#pragma unroll
        for (int dd = 0; dd < 4; ++dd) {
            int d = tid + dd * 256;
            float acc = 0.f;
            for (int i = 0; i < 64; ++i) {
                int k = conn[i * 64 + j];
                if (k >= 0) acc += g_wobj[k] * g_relj[(size_t)k * Dm + d];
            }
            g_ctxo[(size_t)j * Dm + d] = acc;
        }
    }
}

// ---------------- host side ----------------
static float* getsym(const void* s) {
    void* p = nullptr;
    cudaGetSymbolAddress(&p, s);
    return (float*)p;
}

static void gemm_direct(const float* A, int lda, const float* B, int ldb,
                        float* C, int M, int K, int mode) {
    dim3 grid(8, M / 64, 1);
    if (mode == 1)
        k_gemm<1><<<grid, 128>>>(A, lda, B, ldb, C, (size_t)M * 1024, K);
    else
        k_gemm<0><<<grid, 128>>>(A, lda, B, ldb, C, (size_t)M * 1024, K);
}

static void gemm_split(const float* A, int lda, const float* B, int ldb,
                       float* C, float* part, int M, int K, int splitk,
                       const float* bias) {
    dim3 grid(8, M / 64, splitk);
    int Kc = K / splitk;
    size_t strideCz = (size_t)M * 1024;
    k_gemm<0><<<grid, 128>>>(A, lda, B, ldb, part, strideCz, Kc);
    int total = M * 1024;
    k_reduce<<<(total + 255) / 256, 256>>>(part, C, total, splitk, bias);
}

extern "C" void kernel_launch(void* const* d_in, const int* in_sizes, int n_in,
                              void* d_out, int out_size) {
    (void)in_sizes; (void)n_in; (void)out_size;
    const float* v        = (const float*)d_in[0];
    const float* rel      = (const float*)d_in[1];
    const int*   conn     = (const int*)d_in[2];
    const int*   eidx     = (const int*)d_in[4];
    const float* W_sub    = (const float*)d_in[5];
    const float* W_obj    = (const float*)d_in[6];
    const float* W_r2s    = (const float*)d_in[7];
    const float* W_r2o    = (const float*)d_in[8];
    const float* W_joint  = (const float*)d_in[9];
    const float* W_ctx    = (const float*)d_in[10];
    const float* W_relup  = (const float*)d_in[11];
    const float* W_reljnt = (const float*)d_in[12];
    const float* W_relctx = (const float*)d_in[13];
    const float* W_node   = (const float*)d_in[14];
    const float* b_node   = (const float*)d_in[15];
    const float* W_factor = (const float*)d_in[16];

    float* out_f   = (float*)d_out;
    float* rel_out = out_f;
    float* v_out   = out_f + (size_t)Ne * Dm;

    float* Xv     = getsym(g_Xv);
    float* vj     = getsym(g_vj);
    float* Sb     = getsym(g_S);
    float* Ob     = getsym(g_O);
    float* Qs     = getsym(g_Qs);
    float* Qo     = getsym(g_Qo);
    float* Xr     = getsym(g_Xr);
    float* rj     = getsym(g_rj);
    float* relj   = getsym(g_relj);
    float* r2s    = getsym(g_r2s);
    float* r2o    = getsym(g_r2o);
    float* Xrc    = getsym(g_Xrc);
    float* Xc     = getsym(g_Xc);
    float* Xn     = getsym(g_Xn);
    float* relctx = getsym(g_relctx);
    float* vctx   = getsym(g_vctx);
    float* part   = getsym(g_part);

    k_setup<<<512, 256>>>(v, rel, eidx);

    for (int t = 0; t < 2; ++t) {
        // vj = [v, vctx, v*vctx, vctx-v] @ W_joint^T
        k_build_Xv<<<Nn * Dm / 256, 256>>>(v);
        gemm_split(Xv, 4096, W_joint, 4096, vj, part, Nn, 4096, 16, nullptr);

        // rj = [rel, relctx, rel*relctx, rel-relctx] @ W_rel_joint^T  (per edge)
        k_build_Xr<<<Ne * Dm / 256, 256>>>(rel);
        gemm_direct(Xr, 4096, W_reljnt, 4096, rj, Ne, 4096, 0);

        // per-node projections
        gemm_split(vj, 1024, W_relup,        3072, Sb, part, Nn, 1024, 16, nullptr);
        gemm_split(vj, 1024, W_relup + 1024, 3072, Ob, part, Nn, 1024, 16, nullptr);
        gemm_split(vj, 1024, W_sub,          1024, Qs, part, Nn, 1024, 16, nullptr);
        gemm_split(vj, 1024, W_obj,          1024, Qo, part, Nn, 1024, 16, nullptr);

        // rel_j = S[src] + O[dst] + rj @ Wr^T
        gemm_direct(rj, 1024, W_relup + 2048, 3072, relj, Ne, 1024, 1);

        // r2s / r2o projections
        gemm_direct(relj, 1024, W_r2s, 1024, r2s, Ne, 1024, 0);
        gemm_direct(relj, 1024, W_r2o, 1024, r2o, Ne, 1024, 0);

        // scores, softmax, aggregation
        k_score<<<Ne, 128>>>();
        k_softmax<<<1, 128>>>(conn);
        k_ctx<<<dim3(64, 2), 256>>>(conn);

        // vctx = [vctx, ctx_s, ctx_o] @ W_ctx^T
        k_build_Xc<<<Nn * Dm / 256, 256>>>();
        gemm_split(Xc, 3072, W_ctx, 3072, vctx, part, Nn, 3072, 16, nullptr);

        // relctx = [relctx, rel_j] @ W_rel_ctx^T
        k_build_Xrc<<<Ne * Dm / 256, 256>>>();
        gemm_direct(Xrc, 2048, W_relctx, 2048, relctx, Ne, 2048, 0);
    }

    // rel_out = [rel_visual_feat, relctx] @ W_factor^T
    k_build_Xout<<<Ne * Dm / 256, 256>>>(rel);
    gemm_direct(Xrc, 2048, W_factor, 2048, rel_out, Ne, 2048, 0);

    // v_out = [v, vctx] @ W_node^T + b_node  (deg > 0 always by construction)
    k_build_Xn<<<Nn * Dm / 256, 256>>>(v);
    gemm_split(Xn, 2048, W_node, 2048, v_out, part, Nn, 2048, 16, b_node);
}

// round 3
// speedup vs baseline: 1.4492x; 1.4492x over previous
#include <cuda_runtime.h>
#include <cstdint>

#define Dm 1024
#define Nn 64
#define Ne 1024

// ---------------- scratch (device globals; no allocations allowed) ----------------
__device__ float g_vctx[Nn * Dm];
__device__ float g_Xv[Nn * 4 * Dm];
__device__ float g_vj[Nn * Dm];
__device__ float g_S[Nn * Dm];
__device__ float g_O[Nn * Dm];
__device__ float g_Qs[Nn * Dm];
__device__ float g_Qo[Nn * Dm];
__device__ float g_relctx[Ne * Dm];
__device__ float g_Xr[Ne * 4 * Dm];
__device__ float g_rj[Ne * Dm];
__device__ float g_relj[Ne * Dm];
__device__ float g_r2s[Ne * Dm];
__device__ float g_r2o[Ne * Dm];
__device__ float g_Xrc[Ne * 2 * Dm];
__device__ float g_Xc[Nn * 3 * Dm];
__device__ float g_Xn[Nn * 2 * Dm];
__device__ float g_part[16 * Nn * Dm];
__device__ float g_ssbj[Ne];
__device__ float g_sobj[Ne];
__device__ float g_wsbj[Ne];
__device__ float g_wobj[Ne];
__device__ float g_ctxs[Nn * Dm];
__device__ float g_ctxo[Nn * Dm];
__device__ int g_src[Ne];
__device__ int g_dst[Ne];

// ---------------- setup ----------------
__global__ void k_setup(const float* __restrict__ v, const float* __restrict__ rel,
                        const int* __restrict__ eidx) {
    int i0 = blockIdx.x * blockDim.x + threadIdx.x;
    int stride = gridDim.x * blockDim.x;
    for (int t = i0; t < Ne * Dm; t += stride) g_relctx[t] = rel[t];
    for (int t = i0; t < Nn * Dm; t += stride) g_vctx[t] = v[t];
    for (int t = i0; t < Ne; t += stride) {
        int e = eidx[t];
        g_src[t] = e >> 6;
        g_dst[t] = e & 63;
    }
}

// ---------------- concat builders ----------------
__global__ void k_build_Xv(const float* __restrict__ v) {
    int idx = blockIdx.x * blockDim.x + threadIdx.x;
    if (idx >= Nn * Dm) return;
    int i = idx >> 10, d = idx & 1023;
    float a = v[idx], c = g_vctx[idx];
    float* row = g_Xv + (size_t)i * 4096;
    row[d] = a; row[1024 + d] = c; row[2048 + d] = a * c; row[3072 + d] = c - a;
}

__global__ void k_build_Xr(const float* __restrict__ rel) {
    int idx = blockIdx.x * blockDim.x + threadIdx.x;
    if (idx >= Ne * Dm) return;
    int e = idx >> 10, d = idx & 1023;
    float r = rel[idx], c = g_relctx[idx];
    float* row = g_Xr + (size_t)e * 4096;
    row[d] = r; row[1024 + d] = c; row[2048 + d] = r * c; row[3072 + d] = r - c;
}

__global__ void k_build_Xrc() {
    int idx = blockIdx.x * blockDim.x + threadIdx.x;
    if (idx >= Ne * Dm) return;
    int e = idx >> 10, d = idx & 1023;
    float* row = g_Xrc + (size_t)e * 2048;
    row[d] = g_relctx[idx]; row[1024 + d] = g_relj[idx];
}

__global__ void k_build_Xc() {
    int idx = blockIdx.x * blockDim.x + threadIdx.x;
    if (idx >= Nn * Dm) return;
    int i = idx >> 10, d = idx & 1023;
    float* row = g_Xc + (size_t)i * 3072;
    row[d] = g_vctx[idx]; row[1024 + d] = g_ctxs[idx]; row[2048 + d] = g_ctxo[idx];
}

__global__ void k_build_Xout(const float* __restrict__ rel) {
    int idx = blockIdx.x * blockDim.x + threadIdx.x;
    if (idx >= Ne * Dm) return;
    int e = idx >> 10, d = idx & 1023;
    float* row = g_Xrc + (size_t)e * 2048;
    row[d] = rel[idx]; row[1024 + d] = g_relctx[idx];
}

__global__ void k_build_Xn(const float* __restrict__ v) {
    int idx = blockIdx.x * blockDim.x + threadIdx.x;
    if (idx >= Nn * Dm) return;
    int i = idx >> 10, d = idx & 1023;
    float* row = g_Xn + (size_t)i * 2048;
    row[d] = v[idx]; row[1024 + d] = g_vctx[idx];
}

// ======================= tf32 tensor-core NT GEMM =======================
// C[M,1024] = A[M,K] * B[1024,K]^T  via mma.sync.m16n8k8 tf32
// BM=128, BN=64, BK=16, 256 threads = 8 warps (4x2 warp grid, 32x32 per warp)
// MODE 1: epilogue adds g_S[src[m]] + g_O[dst[m]].
#define PADM 136
#define PADN 72

__device__ __forceinline__ uint32_t f2tf32(float x) {
    uint32_t u;
    asm("cvt.rna.tf32.f32 %0, %1;" : "=r"(u) : "f"(x));
    return u;
}

template <int MODE>
__global__ void __launch_bounds__(256) k_tgemm(
    const float* __restrict__ A, int lda,
    const float* __restrict__ B, int ldb,
    float* __restrict__ C, int K) {
    __shared__ uint32_t As[2][16][PADM];
    __shared__ uint32_t Bs[2][16][PADN];

    int tid = threadIdx.x;
    int lane = tid & 31;
    int w = tid >> 5;
    int wm = (w & 3) * 32;     // warp m offset in tile
    int wn = (w >> 2) * 32;    // warp n offset in tile
    int gr = lane >> 2;        // group row 0..7
    int gc = lane & 3;         // group col 0..3

    // gmem load mapping
    int rA = tid & 127;        // A row
    int qA = tid >> 7;         // A quad 0/1 (plus +2 for second load)
    int rB = tid & 63;         // B row
    int qB = tid >> 6;         // B quad 0..3

    const float* Ab = A + (size_t)(blockIdx.y * 128 + rA) * lda;
    const float* Bb = B + (size_t)(blockIdx.x * 64 + rB) * ldb;

    float4 ra0, ra1, rb;
    float c[2][4][4];
#pragma unroll
    for (int mt = 0; mt < 2; ++mt)
#pragma unroll
        for (int nt = 0; nt < 4; ++nt)
#pragma unroll
            for (int q = 0; q < 4; ++q) c[mt][nt][q] = 0.f;

    // prologue: load stage 0
    ra0 = *(const float4*)(Ab + 4 * qA);
    ra1 = *(const float4*)(Ab + 4 * (qA + 2));
    rb  = *(const float4*)(Bb + 4 * qB);
    {
        int k0a = 4 * qA, k1a = 4 * (qA + 2), kb4 = 4 * qB;
        As[0][k0a + 0][rA] = f2tf32(ra0.x); As[0][k0a + 1][rA] = f2tf32(ra0.y);
        As[0][k0a + 2][rA] = f2tf32(ra0.z); As[0][k0a + 3][rA] = f2tf32(ra0.w);
        As[0][k1a + 0][rA] = f2tf32(ra1.x); As[0][k1a + 1][rA] = f2tf32(ra1.y);
        As[0][k1a + 2][rA] = f2tf32(ra1.z); As[0][k1a + 3][rA] = f2tf32(ra1.w);
        Bs[0][kb4 + 0][rB] = f2tf32(rb.x);  Bs[0][kb4 + 1][rB] = f2tf32(rb.y);
        Bs[0][kb4 + 2][rB] = f2tf32(rb.z);  Bs[0][kb4 + 3][rB] = f2tf32(rb.w);
    }
    __syncthreads();

    int buf = 0;
    for (int k0 = 16; k0 <= K; k0 += 16) {
        bool more = (k0 < K);
        if (more) {
            ra0 = *(const float4*)(Ab + k0 + 4 * qA);
            ra1 = *(const float4*)(Ab + k0 + 4 * (qA + 2));
            rb  = *(const float4*)(Bb + k0 + 4 * qB);
        }
        // compute current buffer
#pragma unroll
        for (int ks = 0; ks < 2; ++ks) {
            int kb = ks * 8;
            uint32_t a[2][4], b[4][2];
#pragma unroll
            for (int mt = 0; mt < 2; ++mt) {
                int m0 = wm + mt * 16;
                a[mt][0] = As[buf][kb + gc][m0 + gr];
                a[mt][1] = As[buf][kb + gc][m0 + gr + 8];
                a[mt][2] = As[buf][kb + gc + 4][m0 + gr];
                a[mt][3] = As[buf][kb + gc + 4][m0 + gr + 8];
            }
#pragma unroll
            for (int nt = 0; nt < 4; ++nt) {
                int n0 = wn + nt * 8;
                b[nt][0] = Bs[buf][kb + gc][n0 + gr];
                b[nt][1] = Bs[buf][kb + gc + 4][n0 + gr];
            }
#pragma unroll
            for (int mt = 0; mt < 2; ++mt)
#pragma unroll
                for (int nt = 0; nt < 4; ++nt) {
                    asm volatile(
                        "mma.sync.aligned.m16n8k8.row.col.f32.tf32.tf32.f32 "
                        "{%0,%1,%2,%3}, {%4,%5,%6,%7}, {%8,%9}, {%0,%1,%2,%3};"
                        : "+f"(c[mt][nt][0]), "+f"(c[mt][nt][1]),
                          "+f"(c[mt][nt][2]), "+f"(c[mt][nt][3])
                        : "r"(a[mt][0]), "r"(a[mt][1]), "r"(a[mt][2]), "r"(a[mt][3]),
                          "r"(b[nt][0]), "r"(b[nt][1]));
                }
        }
        if (more) {
            int nb = buf ^ 1;
            int k0a = 4 * qA, k1a = 4 * (qA + 2), kb4 = 4 * qB;
            As[nb][k0a + 0][rA] = f2tf32(ra0.x); As[nb][k0a + 1][rA] = f2tf32(ra0.y);
            As[nb][k0a + 2][rA] = f2tf32(ra0.z); As[nb][k0a + 3][rA] = f2tf32(ra0.w);
            As[nb][k1a + 0][rA] = f2tf32(ra1.x); As[nb][k1a + 1][rA] = f2tf32(ra1.y);
            As[nb][k1a + 2][rA] = f2tf32(ra1.z); As[nb][k1a + 3][rA] = f2tf32(ra1.w);
            Bs[nb][kb4 + 0][rB] = f2tf32(rb.x);  Bs[nb][kb4 + 1][rB] = f2tf32(rb.y);
            Bs[nb][kb4 + 2][rB] = f2tf32(rb.z);  Bs[nb][kb4 + 3][rB] = f2tf32(rb.w);
            buf = nb;
            __syncthreads();
        }
    }

    // epilogue
    int mbase = blockIdx.y * 128 + wm;
    int nbase = blockIdx.x * 64 + wn;
#pragma unroll
    for (int mt = 0; mt < 2; ++mt) {
        int row0 = mbase + mt * 16 + gr;
        int row1 = row0 + 8;
#pragma unroll
        for (int nt = 0; nt < 4; ++nt) {
            int col = nbase + nt * 8 + 2 * gc;
            float2 v0 = make_float2(c[mt][nt][0], c[mt][nt][1]);
            float2 v1 = make_float2(c[mt][nt][2], c[mt][nt][3]);
            if (MODE == 1) {
                const float* s0 = g_S + (size_t)g_src[row0] * 1024 + col;
                const float* o0 = g_O + (size_t)g_dst[row0] * 1024 + col;
                const float* s1 = g_S + (size_t)g_src[row1] * 1024 + col;
                const float* o1 = g_O + (size_t)g_dst[row1] * 1024 + col;
                v0.x += s0[0] + o0[0]; v0.y += s0[1] + o0[1];
                v1.x += s1[0] + o1[0]; v1.y += s1[1] + o1[1];
            }
            *(float2*)(C + (size_t)row0 * 1024 + col) = v0;
            *(float2*)(C + (size_t)row1 * 1024 + col) = v1;
        }
    }
}

// ---------------- FFMA GEMM (kept for small M=64 node GEMMs, split-K) ----------------
__global__ void __launch_bounds__(128) k_gemm(
    const float* __restrict__ A, int lda,
    const float* __restrict__ B, int ldb,
    float* __restrict__ C, size_t strideCz, int Kc) {
    __shared__ float As[16][64];
    __shared__ float Bs[16][128];
    int tid = threadIdx.x;
    int trow = tid >> 4;
    int tcol = tid & 15;
    const float* Ab = A + (size_t)blockIdx.y * 64 * lda + (size_t)blockIdx.z * Kc;
    const float* Bb = B + (size_t)blockIdx.x * 128 * ldb + (size_t)blockIdx.z * Kc;

    float acc[8][8];
#pragma unroll
    for (int i = 0; i < 8; ++i)
#pragma unroll
        for (int j = 0; j < 8; ++j) acc[i][j] = 0.f;

    for (int k0 = 0; k0 < Kc; k0 += 16) {
#pragma unroll
        for (int it = 0; it < 2; ++it) {
            int f = tid + it * 128;
            int r = f >> 2, q = f & 3;
            float4 vv = *(const float4*)(Ab + (size_t)r * lda + k0 + q * 4);
            As[q * 4 + 0][r] = vv.x; As[q * 4 + 1][r] = vv.y;
            As[q * 4 + 2][r] = vv.z; As[q * 4 + 3][r] = vv.w;
        }
#pragma unroll
        for (int it = 0; it < 4; ++it) {
            int f = tid + it * 128;
            int r = f >> 2, q = f & 3;
            float4 vv = *(const float4*)(Bb + (size_t)r * ldb + k0 + q * 4);
            Bs[q * 4 + 0][r] = vv.x; Bs[q * 4 + 1][r] = vv.y;
            Bs[q * 4 + 2][r] = vv.z; Bs[q * 4 + 3][r] = vv.w;
        }
        __syncthreads();
#pragma unroll
        for (int kk = 0; kk < 16; ++kk) {
            float a[8], b[8];
            *(float4*)(a)     = *(const float4*)&As[kk][trow * 8];
            *(float4*)(a + 4) = *(const float4*)&As[kk][trow * 8 + 4];
            *(float4*)(b)     = *(const float4*)&Bs[kk][tcol * 8];
            *(float4*)(b + 4) = *(const float4*)&Bs[kk][tcol * 8 + 4];
#pragma unroll
            for (int i = 0; i < 8; ++i)
#pragma unroll
                for (int j = 0; j < 8; ++j) acc[i][j] += a[i] * b[j];
        }
        __syncthreads();
    }

    float* Cz = C + (size_t)blockIdx.z * strideCz;
    int m0 = blockIdx.y * 64 + trow * 8;
    int n0 = blockIdx.x * 128 + tcol * 8;
#pragma unroll
    for (int i = 0; i < 8; ++i) {
        float* crow = Cz + (size_t)(m0 + i) * 1024 + n0;
        *(float4*)(crow)     = make_float4(acc[i][0], acc[i][1], acc[i][2], acc[i][3]);
        *(float4*)(crow + 4) = make_float4(acc[i][4], acc[i][5], acc[i][6], acc[i][7]);
    }
}

// deterministic split-K reduction (fixed order), optional bias[n]
__global__ void k_reduce(const float* __restrict__ part, float* __restrict__ C,
                         int total, int splitk, const float* __restrict__ bias) {
    int idx = blockIdx.x * 256 + threadIdx.x;
    if (idx >= total) return;
    float s = 0.f;
    for (int z = 0; z < splitk; ++z) s += part[(size_t)z * total + idx];
    if (bias) s += bias[idx & 1023];
    C[idx] = s;
}

// ---------------- per-edge attention scores ----------------
__global__ void k_score() {
    int e = blockIdx.x;
    int tid = threadIdx.x;  // 128
    int s = g_src[e], o = g_dst[e];
    const float* qs = g_Qs + (size_t)s * Dm;
    const float* qo = g_Qo + (size_t)o * Dm;
    const float* rs = g_r2s + (size_t)e * Dm;
    const float* ro = g_r2o + (size_t)e * Dm;
    float a1 = 0.f, a2 = 0.f;
    for (int d = tid; d < Dm; d += 128) {
        a1 += qs[d] * rs[d];
        a2 += qo[d] * ro[d];
    }
#pragma unroll
    for (int off = 16; off; off >>= 1) {
        a1 += __shfl_down_sync(0xffffffffu, a1, off);
        a2 += __shfl_down_sync(0xffffffffu, a2, off);
    }
    __shared__ float sh1[4], sh2[4];
    if ((tid & 31) == 0) { sh1[tid >> 5] = a1; sh2[tid >> 5] = a2; }
    __syncthreads();
    if (tid == 0) {
        float t1 = sh1[0] + sh1[1] + sh1[2] + sh1[3];
        float t2 = sh2[0] + sh2[1] + sh2[2] + sh2[3];
        g_ssbj[e] = t1 * (1.f / 32.f);
        g_sobj[e] = t2 * (1.f / 32.f);
    }
}

// ---------------- masked softmax over rows (sbj) and cols (obj) ----------------
__global__ void k_softmax(const int* __restrict__ conn) {
    int tid = threadIdx.x;  // 128
    float ex[64];
    if (tid < 64) {
        int i = tid;
        float m = -1e30f;
        for (int j = 0; j < 64; ++j) {
            int k = conn[i * 64 + j];
            if (k >= 0) m = fmaxf(m, g_ssbj[k]);
        }
        float sum = 0.f;
        for (int j = 0; j < 64; ++j) {
            int k = conn[i * 64 + j];
            float e = (k >= 0) ? expf(g_ssbj[k] - m) : 0.f;
            ex[j] = e; sum += e;
        }
        float inv = 1.f / sum;
        for (int j = 0; j < 64; ++j) {
            int k = conn[i * 64 + j];
            if (k >= 0) g_wsbj[k] = ex[j] * inv;
        }
    } else {
        int j = tid - 64;
        float m = -1e30f;
        for (int i = 0; i < 64; ++i) {
            int k = conn[i * 64 + j];
            if (k >= 0) m = fmaxf(m, g_sobj[k]);
        }
        float sum = 0.f;
        for (int i = 0; i < 64; ++i) {
            int k = conn[i * 64 + j];
            float e = (k >= 0) ? expf(g_sobj[k] - m) : 0.f;
            ex[i] = e; sum += e;
        }
        float inv = 1.f / sum;
        for (int i = 0; i < 64; ++i) {
            int k = conn[i * 64 + j];
            if (k >= 0) g_wobj[k] = ex[i] * inv;
        }
    }
}

// ---------------- ctx aggregation (deterministic, atomic-free) ----------------
__global__ void k_ctx(const int* __restrict__ conn) {
    int tid = threadIdx.x;  // 256
    if (blockIdx.y == 0) {
        int i = blockIdx.x;
#pragma unroll
        for (int dd = 0; dd < 4; ++dd) {
            int d = tid + dd * 256;
            float acc = 0.f;
            for (int j = 0; j < 64; ++j) {
                int k = conn[i * 64 + j];
                if (k >= 0) acc += g_wsbj[k] * g_relj[(size_t)k * Dm + d];
            }
            g_ctxs[(size_t)i * Dm + d] = acc;
        }
    } else {
        int j = blockIdx.x;
#pragma unroll
        for (int dd = 0; dd < 4; ++dd) {
            int d = tid + dd * 256;
            float acc = 0.f;
            for (int i = 0; i < 64; ++i) {
                int k = conn[i * 64 + j];
                if (k >= 0) acc += g_wobj[k] * g_relj[(size_t)k * Dm + d];
            }
            g_ctxo[(size_t)j * Dm + d] = acc;
        }
    }
}

// ---------------- host side ----------------
static float* getsym(const void* s) {
    void* p = nullptr;
    cudaGetSymbolAddress(&p, s);
    return (float*)p;
}

// tensor-core path for M multiple of 128
static void gemm_t(const float* A, int lda, const float* B, int ldb,
                   float* C, int M, int K, int mode) {
    dim3 grid(16, M / 128);
    if (mode == 1)
        k_tgemm<1><<<grid, 256>>>(A, lda, B, ldb, C, K);
    else
        k_tgemm<0><<<grid, 256>>>(A, lda, B, ldb, C, K);
}

static void gemm_split(const float* A, int lda, const float* B, int ldb,
                       float* C, float* part, int M, int K, int splitk,
                       const float* bias) {
    dim3 grid(8, M / 64, splitk);
    int Kc = K / splitk;
    size_t strideCz = (size_t)M * 1024;
    k_gemm<<<grid, 128>>>(A, lda, B, ldb, part, strideCz, Kc);
    int total = M * 1024;
    k_reduce<<<(total + 255) / 256, 256>>>(part, C, total, splitk, bias);
}

extern "C" void kernel_launch(void* const* d_in, const int* in_sizes, int n_in,
                              void* d_out, int out_size) {
    (void)in_sizes; (void)n_in; (void)out_size;
    const float* v        = (const float*)d_in[0];
    const float* rel      = (const float*)d_in[1];
    const int*   conn     = (const int*)d_in[2];
    const int*   eidx     = (const int*)d_in[4];
    const float* W_sub    = (const float*)d_in[5];
    const float* W_obj    = (const float*)d_in[6];
    const float* W_r2s    = (const float*)d_in[7];
    const float* W_r2o    = (const float*)d_in[8];
    const float* W_joint  = (const float*)d_in[9];
    const float* W_ctx    = (const float*)d_in[10];
    const float* W_relup  = (const float*)d_in[11];
    const float* W_reljnt = (const float*)d_in[12];
    const float* W_relctx = (const float*)d_in[13];
    const float* W_node   = (const float*)d_in[14];
    const float* b_node   = (const float*)d_in[15];
    const float* W_factor = (const float*)d_in[16];

    float* out_f   = (float*)d_out;
    float* rel_out = out_f;
    float* v_out   = out_f + (size_t)Ne * Dm;

    float* Xv     = getsym(g_Xv);
    float* vj     = getsym(g_vj);
    float* Sb     = getsym(g_S);
    float* Ob     = getsym(g_O);
    float* Qs     = getsym(g_Qs);
    float* Qo     = getsym(g_Qo);
    float* Xr     = getsym(g_Xr);
    float* rj     = getsym(g_rj);
    float* relj   = getsym(g_relj);
    float* r2s    = getsym(g_r2s);
    float* r2o    = getsym(g_r2o);
    float* Xrc    = getsym(g_Xrc);
    float* Xc     = getsym(g_Xc);
    float* Xn     = getsym(g_Xn);
    float* relctx = getsym(g_relctx);
    float* vctx   = getsym(g_vctx);
    float* part   = getsym(g_part);

    k_setup<<<512, 256>>>(v, rel, eidx);

    for (int t = 0; t < 2; ++t) {
        // vj = [v, vctx, v*vctx, vctx-v] @ W_joint^T   (M=64, FFMA split-K)
        k_build_Xv<<<Nn * Dm / 256, 256>>>(v);
        gemm_split(Xv, 4096, W_joint, 4096, vj, part, Nn, 4096, 16, nullptr);

        // rj = [rel, relctx, rel*relctx, rel-relctx] @ W_rel_joint^T  (tensor)
        k_build_Xr<<<Ne * Dm / 256, 256>>>(rel);
        gemm_t(Xr, 4096, W_reljnt, 4096, rj, Ne, 4096, 0);

        // per-node projections (M=64, FFMA split-K)
        gemm_split(vj, 1024, W_relup,        3072, Sb, part, Nn, 1024, 16, nullptr);
        gemm_split(vj, 1024, W_relup + 1024, 3072, Ob, part, Nn, 1024, 16, nullptr);
        gemm_split(vj, 1024, W_sub,          1024, Qs, part, Nn, 1024, 16, nullptr);
        gemm_split(vj, 1024, W_obj,          1024, Qo, part, Nn, 1024, 16, nullptr);

        // rel_j = S[src] + O[dst] + rj @ Wr^T   (tensor, fused epilogue)
        gemm_t(rj, 1024, W_relup + 2048, 3072, relj, Ne, 1024, 1);

        // r2s / r2o projections (tensor)
        gemm_t(relj, 1024, W_r2s, 1024, r2s, Ne, 1024, 0);
        gemm_t(relj, 1024, W_r2o, 1024, r2o, Ne, 1024, 0);

        // scores, softmax, aggregation
        k_score<<<Ne, 128>>>();
        k_softmax<<<1, 128>>>(conn);
        k_ctx<<<dim3(64, 2), 256>>>(conn);

        // vctx = [vctx, ctx_s, ctx_o] @ W_ctx^T  (M=64, FFMA split-K)
        k_build_Xc<<<Nn * Dm / 256, 256>>>();
        gemm_split(Xc, 3072, W_ctx, 3072, vctx, part, Nn, 3072, 16, nullptr);

        // relctx = [relctx, rel_j] @ W_rel_ctx^T  (tensor)
        k_build_Xrc<<<Ne * Dm / 256, 256>>>();
        gemm_t(Xrc, 2048, W_relctx, 2048, relctx, Ne, 2048, 0);
    }

    // rel_out = [rel_visual_feat, relctx] @ W_factor^T  (tensor)
    k_build_Xout<<<Ne * Dm / 256, 256>>>(rel);
    gemm_t(Xrc, 2048, W_factor, 2048, rel_out, Ne, 2048, 0);

    // v_out = [v, vctx] @ W_node^T + b_node  (deg > 0 always by construction)
    k_build_Xn<<<Nn * Dm / 256, 256>>>(v);
    gemm_split(Xn, 2048, W_node, 2048, v_out, part, Nn, 2048, 16, b_node);
}

// round 4
// speedup vs baseline: 1.7308x; 1.1943x over previous
#include <cuda_runtime.h>
#include <cstdint>

#define Dm 1024
#define Nn 64
#define Ne 1024

// ---------------- scratch (device globals; no allocations allowed) ----------------
__device__ float g_Xv[Nn * 4 * Dm];
__device__ float g_vj[Nn * Dm];
__device__ float g_SOQQ[Nn * 4 * Dm];   // [S | O | Qs | Qo], ldc 4096
__device__ float g_QQ2[Nn * 2 * Dm];    // [Qs2 | Qo2], ldc 2048
__device__ float g_Xr[Ne * 4 * Dm];
__device__ float g_rj[Ne * Dm];
__device__ float g_relj[Ne * Dm];
__device__ float g_Xrc2[2 * Ne * 2 * Dm];  // ping-pong [relctx | relj]
__device__ float g_Xc[Nn * 3 * Dm];
__device__ float g_Xn[Nn * 2 * Dm];
__device__ float g_part[8 * Nn * 4 * Dm];  // split-K partials (8 MB)
__device__ float g_ssbj[Ne];
__device__ float g_sobj[Ne];
__device__ float g_wsbj[Ne];
__device__ float g_wobj[Ne];
__device__ int g_src[Ne];
__device__ int g_dst[Ne];

// ---------------- setup: indices + initial Xr / Xrc / Xv / Xc ----------------
__global__ void k_setup(const float* __restrict__ v, const float* __restrict__ rel,
                        const int* __restrict__ eidx, float* __restrict__ xrcA) {
    int i0 = blockIdx.x * blockDim.x + threadIdx.x;
    int stride = gridDim.x * blockDim.x;
    for (int t = i0; t < Ne * Dm; t += stride) {
        int e = t >> 10, d = t & 1023;
        float r = rel[t];
        float* xr = g_Xr + (size_t)e * 4096;
        xr[d] = r; xr[1024 + d] = r; xr[2048 + d] = r * r; xr[3072 + d] = 0.f;
        xrcA[(size_t)e * 2048 + d] = r;   // relctx_0 = rel
    }
    for (int t = i0; t < Nn * Dm; t += stride) {
        int i = t >> 10, d = t & 1023;
        float a = v[t];
        float* xv = g_Xv + (size_t)i * 4096;
        xv[d] = a; xv[1024 + d] = a; xv[2048 + d] = a * a; xv[3072 + d] = 0.f;
        g_Xc[(size_t)i * 3072 + d] = a;   // vctx_0 = v
    }
    for (int t = i0; t < Ne; t += stride) {
        int e = eidx[t];
        g_src[t] = e >> 6;
        g_dst[t] = e & 63;
    }
}

// ======================= tf32 tensor-core NT GEMM =======================
// C[M,1024] = A[M,K] * B[1024,K]^T  via mma.sync.m16n8k8 tf32
// BM=128, BN=64, BK=16, 256 thr. MODE 0: plain write C.
// MODE 1 (relj): += SOQQ[src]+SOQQ[dst|+1024]; writes C and xrc_w[row*2048+1024+col].
// MODE 2 (relctx): no C; writes xrc_w and (flag==1) g_Xr; flag==2 final [rel,relctx].
#define PADM 136
#define PADN 72

__device__ __forceinline__ uint32_t f2tf32(float x) {
    uint32_t u;
    asm("cvt.rna.tf32.f32 %0, %1;" : "=r"(u) : "f"(x));
    return u;
}

template <int MODE>
__global__ void __launch_bounds__(256) k_tgemm(
    const float* __restrict__ A, int lda,
    const float* __restrict__ B, int ldb,
    float* __restrict__ C, int K,
    float* __restrict__ xrc_w, const float* __restrict__ rel, int flag) {
    __shared__ uint32_t As[2][16][PADM];
    __shared__ uint32_t Bs[2][16][PADN];

    int tid = threadIdx.x;
    int lane = tid & 31;
    int w = tid >> 5;
    int wm = (w & 3) * 32;
    int wn = (w >> 2) * 32;
    int gr = lane >> 2;
    int gc = lane & 3;

    int rA = tid & 127;
    int qA = tid >> 7;
    int rB = tid & 63;
    int qB = tid >> 6;

    const float* Ab = A + (size_t)(blockIdx.y * 128 + rA) * lda;
    const float* Bb = B + (size_t)(blockIdx.x * 64 + rB) * ldb;

    float4 ra0, ra1, rb;
    float c[2][4][4];
#pragma unroll
    for (int mt = 0; mt < 2; ++mt)
#pragma unroll
        for (int nt = 0; nt < 4; ++nt)
#pragma unroll
            for (int q = 0; q < 4; ++q) c[mt][nt][q] = 0.f;

    ra0 = *(const float4*)(Ab + 4 * qA);
    ra1 = *(const float4*)(Ab + 4 * (qA + 2));
    rb  = *(const float4*)(Bb + 4 * qB);
    {
        int k0a = 4 * qA, k1a = 4 * (qA + 2), kb4 = 4 * qB;
        As[0][k0a + 0][rA] = f2tf32(ra0.x); As[0][k0a + 1][rA] = f2tf32(ra0.y);
        As[0][k0a + 2][rA] = f2tf32(ra0.z); As[0][k0a + 3][rA] = f2tf32(ra0.w);
        As[0][k1a + 0][rA] = f2tf32(ra1.x); As[0][k1a + 1][rA] = f2tf32(ra1.y);
        As[0][k1a + 2][rA] = f2tf32(ra1.z); As[0][k1a + 3][rA] = f2tf32(ra1.w);
        Bs[0][kb4 + 0][rB] = f2tf32(rb.x);  Bs[0][kb4 + 1][rB] = f2tf32(rb.y);
        Bs[0][kb4 + 2][rB] = f2tf32(rb.z);  Bs[0][kb4 + 3][rB] = f2tf32(rb.w);
    }
    __syncthreads();

    int buf = 0;
    for (int k0 = 16; k0 <= K; k0 += 16) {
        bool more = (k0 < K);
        if (more) {
            ra0 = *(const float4*)(Ab + k0 + 4 * qA);
            ra1 = *(const float4*)(Ab + k0 + 4 * (qA + 2));
            rb  = *(const float4*)(Bb + k0 + 4 * qB);
        }
#pragma unroll
        for (int ks = 0; ks < 2; ++ks) {
            int kb = ks * 8;
            uint32_t a[2][4], b[4][2];
#pragma unroll
            for (int mt = 0; mt < 2; ++mt) {
                int m0 = wm + mt * 16;
                a[mt][0] = As[buf][kb + gc][m0 + gr];
                a[mt][1] = As[buf][kb + gc][m0 + gr + 8];
                a[mt][2] = As[buf][kb + gc + 4][m0 + gr];
                a[mt][3] = As[buf][kb + gc + 4][m0 + gr + 8];
            }
#pragma unroll
            for (int nt = 0; nt < 4; ++nt) {
                int n0 = wn + nt * 8;
                b[nt][0] = Bs[buf][kb + gc][n0 + gr];
                b[nt][1] = Bs[buf][kb + gc + 4][n0 + gr];
            }
#pragma unroll
            for (int mt = 0; mt < 2; ++mt)
#pragma unroll
                for (int nt = 0; nt < 4; ++nt) {
                    asm volatile(
                        "mma.sync.aligned.m16n8k8.row.col.f32.tf32.tf32.f32 "
                        "{%0,%1,%2,%3}, {%4,%5,%6,%7}, {%8,%9}, {%0,%1,%2,%3};"
                        : "+f"(c[mt][nt][0]), "+f"(c[mt][nt][1]),
                          "+f"(c[mt][nt][2]), "+f"(c[mt][nt][3])
                        : "r"(a[mt][0]), "r"(a[mt][1]), "r"(a[mt][2]), "r"(a[mt][3]),
                          "r"(b[nt][0]), "r"(b[nt][1]));
                }
        }
        if (more) {
            int nb = buf ^ 1;
            int k0a = 4 * qA, k1a = 4 * (qA + 2), kb4 = 4 * qB;
            As[nb][k0a + 0][rA] = f2tf32(ra0.x); As[nb][k0a + 1][rA] = f2tf32(ra0.y);
            As[nb][k0a + 2][rA] = f2tf32(ra0.z); As[nb][k0a + 3][rA] = f2tf32(ra0.w);
            As[nb][k1a + 0][rA] = f2tf32(ra1.x); As[nb][k1a + 1][rA] = f2tf32(ra1.y);
            As[nb][k1a + 2][rA] = f2tf32(ra1.z); As[nb][k1a + 3][rA] = f2tf32(ra1.w);
            Bs[nb][kb4 + 0][rB] = f2tf32(rb.x);  Bs[nb][kb4 + 1][rB] = f2tf32(rb.y);
            Bs[nb][kb4 + 2][rB] = f2tf32(rb.z);  Bs[nb][kb4 + 3][rB] = f2tf32(rb.w);
            buf = nb;
            __syncthreads();
        }
    }

    int mbase = blockIdx.y * 128 + wm;
    int nbase = blockIdx.x * 64 + wn;
#pragma unroll
    for (int mt = 0; mt < 2; ++mt) {
#pragma unroll
        for (int half = 0; half < 2; ++half) {
            int row = mbase + mt * 16 + gr + half * 8;
#pragma unroll
            for (int nt = 0; nt < 4; ++nt) {
                int col = nbase + nt * 8 + 2 * gc;
                float vx = c[mt][nt][half * 2 + 0];
                float vy = c[mt][nt][half * 2 + 1];
                if (MODE == 0) {
                    *(float2*)(C + (size_t)row * 1024 + col) = make_float2(vx, vy);
                } else if (MODE == 1) {
                    const float* sp = g_SOQQ + (size_t)g_src[row] * 4096 + col;
                    const float* op = g_SOQQ + (size_t)g_dst[row] * 4096 + 1024 + col;
                    vx += sp[0] + op[0];
                    vy += sp[1] + op[1];
                    *(float2*)(C + (size_t)row * 1024 + col) = make_float2(vx, vy);
                    *(float2*)(xrc_w + (size_t)row * 2048 + 1024 + col) = make_float2(vx, vy);
                } else {  // MODE 2
                    float2 rv = *(const float2*)(rel + (size_t)row * 1024 + col);
                    if (flag == 1) {
                        *(float2*)(xrc_w + (size_t)row * 2048 + col) = make_float2(vx, vy);
                        float* xr = g_Xr + (size_t)row * 4096;
                        *(float2*)(xr + col)        = rv;
                        *(float2*)(xr + 1024 + col) = make_float2(vx, vy);
                        *(float2*)(xr + 2048 + col) = make_float2(rv.x * vx, rv.y * vy);
                        *(float2*)(xr + 3072 + col) = make_float2(rv.x - vx, rv.y - vy);
                    } else {  // final: Xrc = [rel, relctx]
                        *(float2*)(xrc_w + (size_t)row * 2048 + col)        = rv;
                        *(float2*)(xrc_w + (size_t)row * 2048 + 1024 + col) = make_float2(vx, vy);
                    }
                }
            }
        }
    }
}

// ---------------- FFMA NT GEMM, M=64, split-K, 4-region B select ----------------
__global__ void __launch_bounds__(128) k_gemm(
    const float* __restrict__ A, int lda,
    const float* __restrict__ B0, const float* __restrict__ B1,
    const float* __restrict__ B2, const float* __restrict__ B3,
    int ldb01, int ldb23,
    float* __restrict__ part, int ldc, size_t strideCz, int Kc) {
    __shared__ float As[16][64];
    __shared__ float Bs[16][128];
    int tid = threadIdx.x;
    int trow = tid >> 4;
    int tcol = tid & 15;
    int bx = blockIdx.x;
    int region = bx >> 3;
    const float* Bp = (region == 0) ? B0 : (region == 1) ? B1 : (region == 2) ? B2 : B3;
    int ldb = (region < 2) ? ldb01 : ldb23;
    const float* Ab = A + (size_t)blockIdx.z * Kc;
    const float* Bb = Bp + (size_t)((bx & 7) * 128) * ldb + (size_t)blockIdx.z * Kc;

    float acc[8][8];
#pragma unroll
    for (int i = 0; i < 8; ++i)
#pragma unroll
        for (int j = 0; j < 8; ++j) acc[i][j] = 0.f;

    for (int k0 = 0; k0 < Kc; k0 += 16) {
#pragma unroll
        for (int it = 0; it < 2; ++it) {
            int f = tid + it * 128;
            int r = f >> 2, q = f & 3;
            float4 vv = *(const float4*)(Ab + (size_t)r * lda + k0 + q * 4);
            As[q * 4 + 0][r] = vv.x; As[q * 4 + 1][r] = vv.y;
            As[q * 4 + 2][r] = vv.z; As[q * 4 + 3][r] = vv.w;
        }
#pragma unroll
        for (int it = 0; it < 4; ++it) {
            int f = tid + it * 128;
            int r = f >> 2, q = f & 3;
            float4 vv = *(const float4*)(Bb + (size_t)r * ldb + k0 + q * 4);
            Bs[q * 4 + 0][r] = vv.x; Bs[q * 4 + 1][r] = vv.y;
            Bs[q * 4 + 2][r] = vv.z; Bs[q * 4 + 3][r] = vv.w;
        }
        __syncthreads();
#pragma unroll
        for (int kk = 0; kk < 16; ++kk) {
            float a[8], b[8];
            *(float4*)(a)     = *(const float4*)&As[kk][trow * 8];
            *(float4*)(a + 4) = *(const float4*)&As[kk][trow * 8 + 4];
            *(float4*)(b)     = *(const float4*)&Bs[kk][tcol * 8];
            *(float4*)(b + 4) = *(const float4*)&Bs[kk][tcol * 8 + 4];
#pragma unroll
            for (int i = 0; i < 8; ++i)
#pragma unroll
                for (int j = 0; j < 8; ++j) acc[i][j] += a[i] * b[j];
        }
        __syncthreads();
    }

    float* Cz = part + (size_t)blockIdx.z * strideCz;
    int m0 = trow * 8;
    int n0g = bx * 128 + tcol * 8;
#pragma unroll
    for (int i = 0; i < 8; ++i) {
        float* crow = Cz + (size_t)(m0 + i) * ldc + n0g;
        *(float4*)(crow)     = make_float4(acc[i][0], acc[i][1], acc[i][2], acc[i][3]);
        *(float4*)(crow + 4) = make_float4(acc[i][4], acc[i][5], acc[i][6], acc[i][7]);
    }
}

// ---------------- FFMA NN GEMM, M=64, split-K, 2-region A/B select ----------------
__global__ void __launch_bounds__(128) k_gemmNN(
    const float* __restrict__ A0, const float* __restrict__ A1, int lda,
    const float* __restrict__ B0, const float* __restrict__ B1, int ldb,
    float* __restrict__ part, int ldc, size_t strideCz, int Kc) {
    __shared__ float As[16][64];
    __shared__ float Bs[16][128];
    int tid = threadIdx.x;
    int trow = tid >> 4;
    int tcol = tid & 15;
    int bx = blockIdx.x;
    int region = bx >> 3;
    const float* A = region ? A1 : A0;
    const float* B = region ? B1 : B0;
    int nl = (bx & 7) * 128;
    int kbase = blockIdx.z * Kc;

    float acc[8][8];
#pragma unroll
    for (int i = 0; i < 8; ++i)
#pragma unroll
        for (int j = 0; j < 8; ++j) acc[i][j] = 0.f;

    for (int k0 = 0; k0 < Kc; k0 += 16) {
#pragma unroll
        for (int it = 0; it < 2; ++it) {
            int f = tid + it * 128;
            int m = f >> 2, q = f & 3;
            float4 av = *(const float4*)(A + (size_t)m * lda + kbase + k0 + q * 4);
            As[q * 4 + 0][m] = av.x; As[q * 4 + 1][m] = av.y;
            As[q * 4 + 2][m] = av.z; As[q * 4 + 3][m] = av.w;
        }
#pragma unroll
        for (int it = 0; it < 4; ++it) {
            int f = tid + it * 128;
            int k = f >> 5, n4 = f & 31;
            *(float4*)&Bs[k][n4 * 4] =
                *(const float4*)(B + (size_t)(kbase + k0 + k) * ldb + nl + n4 * 4);
        }
        __syncthreads();
#pragma unroll
        for (int kk = 0; kk < 16; ++kk) {
            float a[8], b[8];
            *(float4*)(a)     = *(const float4*)&As[kk][trow * 8];
            *(float4*)(a + 4) = *(const float4*)&As[kk][trow * 8 + 4];
            *(float4*)(b)     = *(const float4*)&Bs[kk][tcol * 8];
            *(float4*)(b + 4) = *(const float4*)&Bs[kk][tcol * 8 + 4];
#pragma unroll
            for (int i = 0; i < 8; ++i)
#pragma unroll
                for (int j = 0; j < 8; ++j) acc[i][j] += a[i] * b[j];
        }
        __syncthreads();
    }

    float* Cz = part + (size_t)blockIdx.z * strideCz;
    int m0 = trow * 8;
    int n0g = bx * 128 + tcol * 8;
#pragma unroll
    for (int i = 0; i < 8; ++i) {
        float* crow = Cz + (size_t)(m0 + i) * ldc + n0g;
        *(float4*)(crow)     = make_float4(acc[i][0], acc[i][1], acc[i][2], acc[i][3]);
        *(float4*)(crow + 4) = make_float4(acc[i][4], acc[i][5], acc[i][6], acc[i][7]);
    }
}

// split-K reduce. mode 0: plain. 1: +bias. 2: vctx epilogue (builds Xc/Xv/Xn).
__global__ void k_reduce(const float* __restrict__ part, float* __restrict__ C,
                         int total, int splitk, const float* __restrict__ bias,
                         int mode, const float* __restrict__ v) {
    int idx = blockIdx.x * 256 + threadIdx.x;
    if (idx >= total) return;
    float s = 0.f;
    for (int z = 0; z < splitk; ++z) s += part[(size_t)z * total + idx];
    if (mode == 2) {
        int m = idx >> 10, d = idx & 1023;
        float a = v[idx];
        g_Xc[(size_t)m * 3072 + d] = s;
        float* xv = g_Xv + (size_t)m * 4096;
        xv[d] = a; xv[1024 + d] = s; xv[2048 + d] = a * s; xv[3072 + d] = s - a;
        float* xn = g_Xn + (size_t)m * 2048;
        xn[d] = a; xn[1024 + d] = s;
    } else {
        if (mode == 1) s += bias[idx & 1023];
        C[idx] = s;
    }
}

// ---------------- per-edge attention scores (uses pre-projected Qs2/Qo2) ----------------
__global__ void k_score() {
    int e = blockIdx.x;
    int tid = threadIdx.x;  // 128
    const float* qs = g_QQ2 + (size_t)g_src[e] * 2048;
    const float* qo = g_QQ2 + (size_t)g_dst[e] * 2048 + 1024;
    const float* rj = g_relj + (size_t)e * Dm;
    float a1 = 0.f, a2 = 0.f;
    for (int d = tid; d < Dm; d += 128) {
        float r = rj[d];
        a1 += qs[d] * r;
        a2 += qo[d] * r;
    }
#pragma unroll
    for (int off = 16; off; off >>= 1) {
        a1 += __shfl_down_sync(0xffffffffu, a1, off);
        a2 += __shfl_down_sync(0xffffffffu, a2, off);
    }
    __shared__ float sh1[4], sh2[4];
    if ((tid & 31) == 0) { sh1[tid >> 5] = a1; sh2[tid >> 5] = a2; }
    __syncthreads();
    if (tid == 0) {
        g_ssbj[e] = (sh1[0] + sh1[1] + sh1[2] + sh1[3]) * (1.f / 32.f);
        g_sobj[e] = (sh2[0] + sh2[1] + sh2[2] + sh2[3]) * (1.f / 32.f);
    }
}

// ---------------- masked softmax over rows (sbj) and cols (obj) ----------------
__global__ void k_softmax(const int* __restrict__ conn) {
    int tid = threadIdx.x;  // 128
    float ex[64];
    if (tid < 64) {
        int i = tid;
        float m = -1e30f;
        for (int j = 0; j < 64; ++j) {
            int k = conn[i * 64 + j];
            if (k >= 0) m = fmaxf(m, g_ssbj[k]);
        }
        float sum = 0.f;
        for (int j = 0; j < 64; ++j) {
            int k = conn[i * 64 + j];
            float e = (k >= 0) ? expf(g_ssbj[k] - m) : 0.f;
            ex[j] = e; sum += e;
        }
        float inv = 1.f / sum;
        for (int j = 0; j < 64; ++j) {
            int k = conn[i * 64 + j];
            if (k >= 0) g_wsbj[k] = ex[j] * inv;
        }
    } else {
        int j = tid - 64;
        float m = -1e30f;
        for (int i = 0; i < 64; ++i) {
            int k = conn[i * 64 + j];
            if (k >= 0) m = fmaxf(m, g_sobj[k]);
        }
        float sum = 0.f;
        for (int i = 0; i < 64; ++i) {
            int k = conn[i * 64 + j];
            float e = (k >= 0) ? expf(g_sobj[k] - m) : 0.f;
            ex[i] = e; sum += e;
        }
        float inv = 1.f / sum;
        for (int i = 0; i < 64; ++i) {
            int k = conn[i * 64 + j];
            if (k >= 0) g_wobj[k] = ex[i] * inv;
        }
    }
}

// ---------------- ctx aggregation, writes directly into Xc cols 1024+/2048+ ----------------
__global__ void k_ctx(const int* __restrict__ conn) {
    int tid = threadIdx.x;  // 256
    if (blockIdx.y == 0) {
        int i = blockIdx.x;
#pragma unroll
        for (int dd = 0; dd < 4; ++dd) {
            int d = tid + dd * 256;
            float acc = 0.f;
            for (int j = 0; j < 64; ++j) {
                int k = conn[i * 64 + j];
                if (k >= 0) acc += g_wsbj[k] * g_relj[(size_t)k * Dm + d];
            }
            g_Xc[(size_t)i * 3072 + 1024 + d] = acc;
        }
    } else {
        int j = blockIdx.x;
#pragma unroll
        for (int dd = 0; dd < 4; ++dd) {
            int d = tid + dd * 256;
            float acc = 0.f;
            for (int i = 0; i < 64; ++i) {
                int k = conn[i * 64 + j];
                if (k >= 0) acc += g_wobj[k] * g_relj[(size_t)k * Dm + d];
            }
            g_Xc[(size_t)j * 3072 + 2048 + d] = acc;
        }
    }
}

// ---------------- host side ----------------
static float* getsym(const void* s) {
    void* p = nullptr;
    cudaGetSymbolAddress(&p, s);
    return (float*)p;
}

extern "C" void kernel_launch(void* const* d_in, const int* in_sizes, int n_in,
                              void* d_out, int out_size) {
    (void)in_sizes; (void)n_in; (void)out_size;
    const float* v        = (const float*)d_in[0];
    const float* rel      = (const float*)d_in[1];
    const int*   conn     = (const int*)d_in[2];
    const int*   eidx     = (const int*)d_in[4];
    const float* W_sub    = (const float*)d_in[5];
    const float* W_obj    = (const float*)d_in[6];
    const float* W_r2s    = (const float*)d_in[7];
    const float* W_r2o    = (const float*)d_in[8];
    const float* W_joint  = (const float*)d_in[9];
    const float* W_ctx    = (const float*)d_in[10];
    const float* W_relup  = (const float*)d_in[11];
    const float* W_reljnt = (const float*)d_in[12];
    const float* W_relctx = (const float*)d_in[13];
    const float* W_node   = (const float*)d_in[14];
    const float* b_node   = (const float*)d_in[15];
    const float* W_factor = (const float*)d_in[16];

    float* out_f   = (float*)d_out;
    float* rel_out = out_f;
    float* v_out   = out_f + (size_t)Ne * Dm;

    float* Xv   = getsym(g_Xv);
    float* vj   = getsym(g_vj);
    float* SOQQ = getsym(g_SOQQ);
    float* QQ2  = getsym(g_QQ2);
    float* Xr   = getsym(g_Xr);
    float* rj   = getsym(g_rj);
    float* relj = getsym(g_relj);
    float* XrcB = getsym(g_Xrc2);
    float* Xc   = getsym(g_Xc);
    float* Xn   = getsym(g_Xn);
    float* part = getsym(g_part);
    float* xrc[2] = {XrcB, XrcB + (size_t)Ne * 2048};

    k_setup<<<512, 256>>>(v, rel, eidx, xrc[0]);

    for (int t = 0; t < 2; ++t) {
        // vj = Xv @ W_joint^T   (M=64, K=4096, split-K 16)
        k_gemm<<<dim3(8, 1, 16), 128>>>(Xv, 4096, W_joint, W_joint, W_joint, W_joint,
                                        4096, 4096, part, 1024, 65536, 256);
        k_reduce<<<256, 256>>>(part, vj, 65536, 16, nullptr, 0, nullptr);

        // rj = Xr @ W_rel_joint^T  (tensor, K=4096)
        k_tgemm<0><<<dim3(16, 8), 256>>>(Xr, 4096, W_reljnt, 4096, rj, 4096,
                                         nullptr, nullptr, 0);

        // node batch: SOQQ = vj @ [Ws | Wo | W_sub | W_obj]^T  (N=4096, split-K 8)
        k_gemm<<<dim3(32, 1, 8), 128>>>(vj, 1024, W_relup, W_relup + 1024, W_sub, W_obj,
                                        3072, 1024, part, 4096, 262144, 128);
        k_reduce<<<1024, 256>>>(part, SOQQ, 262144, 8, nullptr, 0, nullptr);

        // relj = S[src] + O[dst] + rj @ Wr^T  (tensor, fused epi -> Xrc[t] 2nd half)
        k_tgemm<1><<<dim3(16, 8), 256>>>(rj, 1024, W_relup + 2048, 3072, relj, 1024,
                                         xrc[t], nullptr, 0);

        // QQ2 = [Qs @ W_r2s | Qo @ W_r2o]  (NN, N=2048, split-K 8)
        k_gemmNN<<<dim3(16, 1, 8), 128>>>(SOQQ + 2048, SOQQ + 3072, 4096,
                                          W_r2s, W_r2o, 1024,
                                          part, 2048, 131072, 128);
        k_reduce<<<512, 256>>>(part, QQ2, 131072, 8, nullptr, 0, nullptr);

        // scores, softmax, aggregation (ctx writes into Xc)
        k_score<<<Ne, 128>>>();
        k_softmax<<<1, 128>>>(conn);
        k_ctx<<<dim3(64, 2), 256>>>(conn);

        // vctx = Xc @ W_ctx^T  (M=64, K=3072, split-K 16; reduce builds Xc/Xv/Xn)
        k_gemm<<<dim3(8, 1, 16), 128>>>(Xc, 3072, W_ctx, W_ctx, W_ctx, W_ctx,
                                        3072, 3072, part, 1024, 65536, 192);
        k_reduce<<<256, 256>>>(part, nullptr, 65536, 16, nullptr, 2, v);

        // relctx = Xrc[t] @ W_rel_ctx^T  (tensor; epi writes Xrc[t^1] + Xr or final Xout)
        k_tgemm<2><<<dim3(16, 8), 256>>>(xrc[t], 2048, W_relctx, 2048, nullptr, 2048,
                                         xrc[t ^ 1], rel, (t == 0) ? 1 : 2);
    }

    // rel_out = [rel, relctx] @ W_factor^T  (tensor; Xrc[0] holds [rel, relctx])
    k_tgemm<0><<<dim3(16, 8), 256>>>(xrc[0], 2048, W_factor, 2048, rel_out, 2048,
                                     nullptr, nullptr, 0);

    // v_out = Xn @ W_node^T + b_node  (deg > 0 always by construction)
    k_gemm<<<dim3(8, 1, 16), 128>>>(Xn, 2048, W_node, W_node, W_node, W_node,
                                    2048, 2048, part, 1024, 65536, 128);
    k_reduce<<<256, 256>>>(part, v_out, 65536, 16, b_node, 1, nullptr);
}

// round 6
// speedup vs baseline: 1.8277x; 1.0560x over previous
#include <cuda_runtime.h>
#include <cstdint>

#define Dm 1024
#define Nn 64
#define Ne 1024

// ---------------- scratch (device globals; no allocations allowed) ----------------
__device__ float g_Xv[Nn * 3 * Dm];      // t0: [v, v^2] ld2048; t1: [v,vctx,v*vctx] ld3072
__device__ float g_vj[Nn * Dm];
__device__ float g_SOQQ[Nn * 4 * Dm];    // [S | O | Qs | Qo], ldc 4096
__device__ float g_QQ2[Nn * 2 * Dm];     // [Qs2 | Qo2], ldc 2048
__device__ float g_Xr[Ne * 3 * Dm];      // t0: [rel, rel^2] ld2048; t1: [rel,ctx,rel*ctx] ld3072
__device__ float g_rj[Ne * Dm];
__device__ float g_relj[Ne * Dm];
__device__ float g_Xrc2[2 * Ne * 2 * Dm];  // ping-pong [relctx | relj]
__device__ float g_Xc[Nn * 3 * Dm];
__device__ float g_Xn[Nn * 2 * Dm];
__device__ float g_part[8 * Nn * 4 * Dm];
__device__ float g_WjA[Dm * 2048];       // [Wj1+Wj2 | Wj3]
__device__ float g_WjB[Dm * 3072];       // [Wj1-Wj4 | Wj2+Wj4 | Wj3]   (vj: 4th slot = c - a)
__device__ float g_WrA[Dm * 2048];
__device__ float g_WrB[Dm * 3072];       // [Wr1+Wr4 | Wr2-Wr4 | Wr3]   (rj: 4th slot = r - c)
__device__ float g_ssbj[Ne];
__device__ float g_sobj[Ne];
__device__ float g_wsbj[Ne];
__device__ float g_wobj[Ne];
__device__ int g_src[Ne];
__device__ int g_dst[Ne];

// ---------------- weight folding ----------------
// vj input is [a, c, a*c, c-a]  ->  a@(W1-W4) + c@(W2+W4) + (a*c)@W3
// rj input is [r, c, r*c, r-c]  ->  r@(W1+W4) + c@(W2-W4) + (r*c)@W3
__global__ void k_wcomb(const float* __restrict__ Wj, const float* __restrict__ Wr) {
    int idx = blockIdx.x * 256 + threadIdx.x;
    if (idx >= Dm * Dm) return;
    int o = idx >> 10, d = idx & 1023;
    {
        const float* r = Wj + (size_t)o * 4096;
        float w1 = r[d], w2 = r[1024 + d], w3 = r[2048 + d], w4 = r[3072 + d];
        g_WjA[(size_t)o * 2048 + d] = w1 + w2;
        g_WjA[(size_t)o * 2048 + 1024 + d] = w3;
        g_WjB[(size_t)o * 3072 + d] = w1 - w4;          // vj sign
        g_WjB[(size_t)o * 3072 + 1024 + d] = w2 + w4;   // vj sign
        g_WjB[(size_t)o * 3072 + 2048 + d] = w3;
    }
    {
        const float* r = Wr + (size_t)o * 4096;
        float w1 = r[d], w2 = r[1024 + d], w3 = r[2048 + d], w4 = r[3072 + d];
        g_WrA[(size_t)o * 2048 + d] = w1 + w2;
        g_WrA[(size_t)o * 2048 + 1024 + d] = w3;
        g_WrB[(size_t)o * 3072 + d] = w1 + w4;          // rj sign
        g_WrB[(size_t)o * 3072 + 1024 + d] = w2 - w4;   // rj sign
        g_WrB[(size_t)o * 3072 + 2048 + d] = w3;
    }
}

// ---------------- setup ----------------
__global__ void k_setup(const float* __restrict__ v, const float* __restrict__ rel,
                        const int* __restrict__ eidx, float* __restrict__ xrcA) {
    int i0 = blockIdx.x * blockDim.x + threadIdx.x;
    int stride = gridDim.x * blockDim.x;
    for (int t = i0; t < Ne * Dm; t += stride) {
        int e = t >> 10, d = t & 1023;
        float r = rel[t];
        float* xr = g_Xr + (size_t)e * 2048;
        xr[d] = r; xr[1024 + d] = r * r;
        xrcA[(size_t)e * 2048 + d] = r;
    }
    for (int t = i0; t < Nn * Dm; t += stride) {
        int i = t >> 10, d = t & 1023;
        float a = v[t];
        float* xv = g_Xv + (size_t)i * 2048;
        xv[d] = a; xv[1024 + d] = a * a;
        g_Xc[(size_t)i * 3072 + d] = a;
    }
    for (int t = i0; t < Ne; t += stride) {
        int e = eidx[t];
        g_src[t] = e >> 6;
        g_dst[t] = e & 63;
    }
}

// ======================= tf32 tensor-core NT GEMM (paired 64-bit LDS) ==========
// C[M,1024] = A[M,K] * B[1024,K]^T, BM=128 BN=64 BK=16, 256 thr, 8 warps 32x32.
// Smem stores uint2 pairs (k, k+4); row pads 132/68 -> conflict-free LDS.64.
// MODE 0: write C. MODE 1: += SOQQ[src]+SOQQ[dst+1024], also writes xrc 2nd half.
// MODE 2: no C; flag==1 -> writes xrc relctx + Xr=[rel,ctx,rel*ctx] (ld 3072);
//         flag==2 -> writes final xrc=[rel, relctx].
#define PADM2 132
#define PADN2 68

__device__ __forceinline__ uint32_t f2tf32(float x) {
    uint32_t u;
    asm("cvt.rna.tf32.f32 %0, %1;" : "=r"(u) : "f"(x));
    return u;
}

template <int MODE>
__global__ void __launch_bounds__(256) k_tgemm(
    const float* __restrict__ A, int lda,
    const float* __restrict__ B, int ldb,
    float* __restrict__ C, int K,
    float* __restrict__ xrc_w, const float* __restrict__ rel, int flag) {
    __shared__ uint2 As2[2][8][PADM2];
    __shared__ uint2 Bs2[2][8][PADN2];

    int tid = threadIdx.x;
    int lane = tid & 31;
    int w = tid >> 5;
    int wm = (w & 3) * 32;
    int wn = (w >> 2) * 32;
    int gr = lane >> 2;
    int gc = lane & 3;

    int rA = tid & 127;
    int hA = tid >> 7;
    int rB = tid & 63;
    int hB = (tid >> 6) & 1;
    bool doB = tid < 128;

    const float* Ab = A + (size_t)(blockIdx.y * 128 + rA) * lda + hA * 8;
    const float* Bb = B + (size_t)(blockIdx.x * 64 + rB) * ldb + hB * 8;

    float4 fa0, fa1, fb0, fb1;
    float c[2][4][4];
#pragma unroll
    for (int mt = 0; mt < 2; ++mt)
#pragma unroll
        for (int nt = 0; nt < 4; ++nt)
#pragma unroll
            for (int q = 0; q < 4; ++q) c[mt][nt][q] = 0.f;

    fa0 = *(const float4*)(Ab);
    fa1 = *(const float4*)(Ab + 4);
    if (doB) { fb0 = *(const float4*)(Bb); fb1 = *(const float4*)(Bb + 4); }
    As2[0][hA * 4 + 0][rA] = make_uint2(f2tf32(fa0.x), f2tf32(fa1.x));
    As2[0][hA * 4 + 1][rA] = make_uint2(f2tf32(fa0.y), f2tf32(fa1.y));
    As2[0][hA * 4 + 2][rA] = make_uint2(f2tf32(fa0.z), f2tf32(fa1.z));
    As2[0][hA * 4 + 3][rA] = make_uint2(f2tf32(fa0.w), f2tf32(fa1.w));
    if (doB) {
        Bs2[0][hB * 4 + 0][rB] = make_uint2(f2tf32(fb0.x), f2tf32(fb1.x));
        Bs2[0][hB * 4 + 1][rB] = make_uint2(f2tf32(fb0.y), f2tf32(fb1.y));
        Bs2[0][hB * 4 + 2][rB] = make_uint2(f2tf32(fb0.z), f2tf32(fb1.z));
        Bs2[0][hB * 4 + 3][rB] = make_uint2(f2tf32(fb0.w), f2tf32(fb1.w));
    }
    __syncthreads();

    int buf = 0;
    for (int k0 = 16; k0 <= K; k0 += 16) {
        bool more = (k0 < K);
        if (more) {
            fa0 = *(const float4*)(Ab + k0);
            fa1 = *(const float4*)(Ab + k0 + 4);
            if (doB) { fb0 = *(const float4*)(Bb + k0); fb1 = *(const float4*)(Bb + k0 + 4); }
        }
#pragma unroll
        for (int ks = 0; ks < 2; ++ks) {
            int kb = ks * 4 + gc;
            uint2 qa00 = As2[buf][kb][wm + gr];
            uint2 qa01 = As2[buf][kb][wm + gr + 8];
            uint2 qa10 = As2[buf][kb][wm + 16 + gr];
            uint2 qa11 = As2[buf][kb][wm + 16 + gr + 8];
            uint2 qb0 = Bs2[buf][kb][wn + gr];
            uint2 qb1 = Bs2[buf][kb][wn + 8 + gr];
            uint2 qb2 = Bs2[buf][kb][wn + 16 + gr];
            uint2 qb3 = Bs2[buf][kb][wn + 24 + gr];
            uint32_t a[2][4];
            a[0][0] = qa00.x; a[0][1] = qa01.x; a[0][2] = qa00.y; a[0][3] = qa01.y;
            a[1][0] = qa10.x; a[1][1] = qa11.x; a[1][2] = qa10.y; a[1][3] = qa11.y;
            uint32_t b[4][2];
            b[0][0] = qb0.x; b[0][1] = qb0.y;
            b[1][0] = qb1.x; b[1][1] = qb1.y;
            b[2][0] = qb2.x; b[2][1] = qb2.y;
            b[3][0] = qb3.x; b[3][1] = qb3.y;
#pragma unroll
            for (int mt = 0; mt < 2; ++mt)
#pragma unroll
                for (int nt = 0; nt < 4; ++nt) {
                    asm volatile(
                        "mma.sync.aligned.m16n8k8.row.col.f32.tf32.tf32.f32 "
                        "{%0,%1,%2,%3}, {%4,%5,%6,%7}, {%8,%9}, {%0,%1,%2,%3};"
                        : "+f"(c[mt][nt][0]), "+f"(c[mt][nt][1]),
                          "+f"(c[mt][nt][2]), "+f"(c[mt][nt][3])
                        : "r"(a[mt][0]), "r"(a[mt][1]), "r"(a[mt][2]), "r"(a[mt][3]),
                          "r"(b[nt][0]), "r"(b[nt][1]));
                }
        }
        if (more) {
            int nb = buf ^ 1;
            As2[nb][hA * 4 + 0][rA] = make_uint2(f2tf32(fa0.x), f2tf32(fa1.x));
            As2[nb][hA * 4 + 1][rA] = make_uint2(f2tf32(fa0.y), f2tf32(fa1.y));
            As2[nb][hA * 4 + 2][rA] = make_uint2(f2tf32(fa0.z), f2tf32(fa1.z));
            As2[nb][hA * 4 + 3][rA] = make_uint2(f2tf32(fa0.w), f2tf32(fa1.w));
            if (doB) {
                Bs2[nb][hB * 4 + 0][rB] = make_uint2(f2tf32(fb0.x), f2tf32(fb1.x));
                Bs2[nb][hB * 4 + 1][rB] = make_uint2(f2tf32(fb0.y), f2tf32(fb1.y));
                Bs2[nb][hB * 4 + 2][rB] = make_uint2(f2tf32(fb0.z), f2tf32(fb1.z));
                Bs2[nb][hB * 4 + 3][rB] = make_uint2(f2tf32(fb0.w), f2tf32(fb1.w));
            }
            buf = nb;
            __syncthreads();
        }
    }

    int mbase = blockIdx.y * 128 + wm;
    int nbase = blockIdx.x * 64 + wn;
#pragma unroll
    for (int mt = 0; mt < 2; ++mt) {
#pragma unroll
        for (int half = 0; half < 2; ++half) {
            int row = mbase + mt * 16 + gr + half * 8;
#pragma unroll
            for (int nt = 0; nt < 4; ++nt) {
                int col = nbase + nt * 8 + 2 * gc;
                float vx = c[mt][nt][half * 2 + 0];
                float vy = c[mt][nt][half * 2 + 1];
                if (MODE == 0) {
                    *(float2*)(C + (size_t)row * 1024 + col) = make_float2(vx, vy);
                } else if (MODE == 1) {
                    const float* sp = g_SOQQ + (size_t)g_src[row] * 4096 + col;
                    const float* op = g_SOQQ + (size_t)g_dst[row] * 4096 + 1024 + col;
                    vx += sp[0] + op[0];
                    vy += sp[1] + op[1];
                    *(float2*)(C + (size_t)row * 1024 + col) = make_float2(vx, vy);
                    *(float2*)(xrc_w + (size_t)row * 2048 + 1024 + col) = make_float2(vx, vy);
                } else {  // MODE 2
                    float2 rv = *(const float2*)(rel + (size_t)row * 1024 + col);
                    if (flag == 1) {
                        *(float2*)(xrc_w + (size_t)row * 2048 + col) = make_float2(vx, vy);
                        float* xr = g_Xr + (size_t)row * 3072;
                        *(float2*)(xr + col)        = rv;
                        *(float2*)(xr + 1024 + col) = make_float2(vx, vy);
                        *(float2*)(xr + 2048 + col) = make_float2(rv.x * vx, rv.y * vy);
                    } else {
                        *(float2*)(xrc_w + (size_t)row * 2048 + col)        = rv;
                        *(float2*)(xrc_w + (size_t)row * 2048 + 1024 + col) = make_float2(vx, vy);
                    }
                }
            }
        }
    }
}

// ---------------- FFMA NT GEMM, M=64, split-K, 4-region B select ----------------
__global__ void __launch_bounds__(128) k_gemm(
    const float* __restrict__ A, int lda,
    const float* __restrict__ B0, const float* __restrict__ B1,
    const float* __restrict__ B2, const float* __restrict__ B3,
    int ldb01, int ldb23,
    float* __restrict__ part, int ldc, size_t strideCz, int Kc) {
    __shared__ float As[16][64];
    __shared__ float Bs[16][128];
    int tid = threadIdx.x;
    int trow = tid >> 4;
    int tcol = tid & 15;
    int bx = blockIdx.x;
    int region = bx >> 3;
    const float* Bp = (region == 0) ? B0 : (region == 1) ? B1 : (region == 2) ? B2 : B3;
    int ldb = (region < 2) ? ldb01 : ldb23;
    const float* Ab = A + (size_t)blockIdx.z * Kc;
    const float* Bb = Bp + (size_t)((bx & 7) * 128) * ldb + (size_t)blockIdx.z * Kc;

    float acc[8][8];
#pragma unroll
    for (int i = 0; i < 8; ++i)
#pragma unroll
        for (int j = 0; j < 8; ++j) acc[i][j] = 0.f;

    for (int k0 = 0; k0 < Kc; k0 += 16) {
#pragma unroll
        for (int it = 0; it < 2; ++it) {
            int f = tid + it * 128;
            int r = f >> 2, q = f & 3;
            float4 vv = *(const float4*)(Ab + (size_t)r * lda + k0 + q * 4);
            As[q * 4 + 0][r] = vv.x; As[q * 4 + 1][r] = vv.y;
            As[q * 4 + 2][r] = vv.z; As[q * 4 + 3][r] = vv.w;
        }
#pragma unroll
        for (int it = 0; it < 4; ++it) {
            int f = tid + it * 128;
            int r = f >> 2, q = f & 3;
            float4 vv = *(const float4*)(Bb + (size_t)r * ldb + k0 + q * 4);
            Bs[q * 4 + 0][r] = vv.x; Bs[q * 4 + 1][r] = vv.y;
            Bs[q * 4 + 2][r] = vv.z; Bs[q * 4 + 3][r] = vv.w;
        }
        __syncthreads();
#pragma unroll
        for (int kk = 0; kk < 16; ++kk) {
            float a[8], b[8];
            *(float4*)(a)     = *(const float4*)&As[kk][trow * 8];
            *(float4*)(a + 4) = *(const float4*)&As[kk][trow * 8 + 4];
            *(float4*)(b)     = *(const float4*)&Bs[kk][tcol * 8];
            *(float4*)(b + 4) = *(const float4*)&Bs[kk][tcol * 8 + 4];
#pragma unroll
            for (int i = 0; i < 8; ++i)
#pragma unroll
                for (int j = 0; j < 8; ++j) acc[i][j] += a[i] * b[j];
        }
        __syncthreads();
    }

    float* Cz = part + (size_t)blockIdx.z * strideCz;
    int m0 = trow * 8;
    int n0g = bx * 128 + tcol * 8;
#pragma unroll
    for (int i = 0; i < 8; ++i) {
        float* crow = Cz + (size_t)(m0 + i) * ldc + n0g;
        *(float4*)(crow)     = make_float4(acc[i][0], acc[i][1], acc[i][2], acc[i][3]);
        *(float4*)(crow + 4) = make_float4(acc[i][4], acc[i][5], acc[i][6], acc[i][7]);
    }
}

// ---------------- FFMA NN GEMM, M=64, split-K, 2-region A/B select ----------------
__global__ void __launch_bounds__(128) k_gemmNN(
    const float* __restrict__ A0, const float* __restrict__ A1, int lda,
    const float* __restrict__ B0, const float* __restrict__ B1, int ldb,
    float* __restrict__ part, int ldc, size_t strideCz, int Kc) {
    __shared__ float As[16][64];
    __shared__ float Bs[16][128];
    int tid = threadIdx.x;
    int trow = tid >> 4;
    int tcol = tid & 15;
    int bx = blockIdx.x;
    int region = bx >> 3;
    const float* A = region ? A1 : A0;
    const float* B = region ? B1 : B0;
    int nl = (bx & 7) * 128;
    int kbase = blockIdx.z * Kc;

    float acc[8][8];
#pragma unroll
    for (int i = 0; i < 8; ++i)
#pragma unroll
        for (int j = 0; j < 8; ++j) acc[i][j] = 0.f;

    for (int k0 = 0; k0 < Kc; k0 += 16) {
#pragma unroll
        for (int it = 0; it < 2; ++it) {
            int f = tid + it * 128;
            int m = f >> 2, q = f & 3;
            float4 av = *(const float4*)(A + (size_t)m * lda + kbase + k0 + q * 4);
            As[q * 4 + 0][m] = av.x; As[q * 4 + 1][m] = av.y;
            As[q * 4 + 2][m] = av.z; As[q * 4 + 3][m] = av.w;
        }
#pragma unroll
        for (int it = 0; it < 4; ++it) {
            int f = tid + it * 128;
            int k = f >> 5, n4 = f & 31;
            *(float4*)&Bs[k][n4 * 4] =
                *(const float4*)(B + (size_t)(kbase + k0 + k) * ldb + nl + n4 * 4);
        }
        __syncthreads();
#pragma unroll
        for (int kk = 0; kk < 16; ++kk) {
            float a[8], b[8];
            *(float4*)(a)     = *(const float4*)&As[kk][trow * 8];
            *(float4*)(a + 4) = *(const float4*)&As[kk][trow * 8 + 4];
            *(float4*)(b)     = *(const float4*)&Bs[kk][tcol * 8];
            *(float4*)(b + 4) = *(const float4*)&Bs[kk][tcol * 8 + 4];
#pragma unroll
            for (int i = 0; i < 8; ++i)
#pragma unroll
                for (int j = 0; j < 8; ++j) acc[i][j] += a[i] * b[j];
        }
        __syncthreads();
    }

    float* Cz = part + (size_t)blockIdx.z * strideCz;
    int m0 = trow * 8;
    int n0g = bx * 128 + tcol * 8;
#pragma unroll
    for (int i = 0; i < 8; ++i) {
        float* crow = Cz + (size_t)(m0 + i) * ldc + n0g;
        *(float4*)(crow)     = make_float4(acc[i][0], acc[i][1], acc[i][2], acc[i][3]);
        *(float4*)(crow + 4) = make_float4(acc[i][4], acc[i][5], acc[i][6], acc[i][7]);
    }
}

// split-K reduce. mode 0: plain. 1: +bias. 2: vctx epilogue (builds Xc/Xv/Xn).
__global__ void k_reduce(const float* __restrict__ part, float* __restrict__ C,
                         int total, int splitk, const float* __restrict__ bias,
                         int mode, const float* __restrict__ v) {
    int idx = blockIdx.x * 256 + threadIdx.x;
    if (idx >= total) return;
    float s = 0.f;
    for (int z = 0; z < splitk; ++z) s += part[(size_t)z * total + idx];
    if (mode == 2) {
        int m = idx >> 10, d = idx & 1023;
        float a = v[idx];
        g_Xc[(size_t)m * 3072 + d] = s;
        float* xv = g_Xv + (size_t)m * 3072;
        xv[d] = a; xv[1024 + d] = s; xv[2048 + d] = a * s;
        float* xn = g_Xn + (size_t)m * 2048;
        xn[d] = a; xn[1024 + d] = s;
    } else {
        if (mode == 1) s += bias[idx & 1023];
        C[idx] = s;
    }
}

// ---------------- per-edge attention scores ----------------
__global__ void k_score() {
    int e = blockIdx.x;
    int tid = threadIdx.x;  // 128
    const float* qs = g_QQ2 + (size_t)g_src[e] * 2048;
    const float* qo = g_QQ2 + (size_t)g_dst[e] * 2048 + 1024;
    const float* rj = g_relj + (size_t)e * Dm;
    float a1 = 0.f, a2 = 0.f;
    for (int d = tid; d < Dm; d += 128) {
        float r = rj[d];
        a1 += qs[d] * r;
        a2 += qo[d] * r;
    }
#pragma unroll
    for (int off = 16; off; off >>= 1) {
        a1 += __shfl_down_sync(0xffffffffu, a1, off);
        a2 += __shfl_down_sync(0xffffffffu, a2, off);
    }
    __shared__ float sh1[4], sh2[4];
    if ((tid & 31) == 0) { sh1[tid >> 5] = a1; sh2[tid >> 5] = a2; }
    __syncthreads();
    if (tid == 0) {
        g_ssbj[e] = (sh1[0] + sh1[1] + sh1[2] + sh1[3]) * (1.f / 32.f);
        g_sobj[e] = (sh2[0] + sh2[1] + sh2[2] + sh2[3]) * (1.f / 32.f);
    }
}

// ---------------- masked softmax ----------------
__global__ void k_softmax(const int* __restrict__ conn) {
    int tid = threadIdx.x;  // 128
    float ex[64];
    if (tid < 64) {
        int i = tid;
        float m = -1e30f;
        for (int j = 0; j < 64; ++j) {
            int k = conn[i * 64 + j];
            if (k >= 0) m = fmaxf(m, g_ssbj[k]);
        }
        float sum = 0.f;
        for (int j = 0; j < 64; ++j) {
            int k = conn[i * 64 + j];
            float e = (k >= 0) ? expf(g_ssbj[k] - m) : 0.f;
            ex[j] = e; sum += e;
        }
        float inv = 1.f / sum;
        for (int j = 0; j < 64; ++j) {
            int k = conn[i * 64 + j];
            if (k >= 0) g_wsbj[k] = ex[j] * inv;
        }
    } else {
        int j = tid - 64;
        float m = -1e30f;
        for (int i = 0; i < 64; ++i) {
            int k = conn[i * 64 + j];
            if (k >= 0) m = fmaxf(m, g_sobj[k]);
        }
        float sum = 0.f;
        for (int i = 0; i < 64; ++i) {
            int k = conn[i * 64 + j];
            float e = (k >= 0) ? expf(g_sobj[k] - m) : 0.f;
            ex[i] = e; sum += e;
        }
        float inv = 1.f / sum;
        for (int i = 0; i < 64; ++i) {
            int k = conn[i * 64 + j];
            if (k >= 0) g_wobj[k] = ex[i] * inv;
        }
    }
}

// ---------------- ctx aggregation -> Xc cols 1024+/2048+ ----------------
__global__ void k_ctx(const int* __restrict__ conn) {
    int tid = threadIdx.x;  // 256
    if (blockIdx.y == 0) {
        int i = blockIdx.x;
#pragma unroll
        for (int dd = 0; dd < 4; ++dd) {
            int d = tid + dd * 256;
            float acc = 0.f;
            for (int j = 0; j < 64; ++j) {
                int k = conn[i * 64 + j];
                if (k >= 0) acc += g_wsbj[k] * g_relj[(size_t)k * Dm + d];
            }
            g_Xc[(size_t)i * 3072 + 1024 + d] = acc;
        }
    } else {
        int j = blockIdx.x;
#pragma unroll
        for (int dd = 0; dd < 4; ++dd) {
            int d = tid + dd * 256;
            float acc = 0.f;
            for (int i = 0; i < 64; ++i) {
                int k = conn[i * 64 + j];
                if (k >= 0) acc += g_wobj[k] * g_relj[(size_t)k * Dm + d];
            }
            g_Xc[(size_t)j * 3072 + 2048 + d] = acc;
        }
    }
}

// ---------------- host side ----------------
static float* getsym(const void* s) {
    void* p = nullptr;
    cudaGetSymbolAddress(&p, s);
    return (float*)p;
}

extern "C" void kernel_launch(void* const* d_in, const int* in_sizes, int n_in,
                              void* d_out, int out_size) {
    (void)in_sizes; (void)n_in; (void)out_size;
    const float* v        = (const float*)d_in[0];
    const float* rel      = (const float*)d_in[1];
    const int*   conn     = (const int*)d_in[2];
    const int*   eidx     = (const int*)d_in[4];
    const float* W_sub    = (const float*)d_in[5];
    const float* W_obj    = (const float*)d_in[6];
    const float* W_r2s    = (const float*)d_in[7];
    const float* W_r2o    = (const float*)d_in[8];
    const float* W_joint  = (const float*)d_in[9];
    const float* W_ctx    = (const float*)d_in[10];
    const float* W_relup  = (const float*)d_in[11];
    const float* W_reljnt = (const float*)d_in[12];
    const float* W_relctx = (const float*)d_in[13];
    const float* W_node   = (const float*)d_in[14];
    const float* b_node   = (const float*)d_in[15];
    const float* W_factor = (const float*)d_in[16];

    float* out_f   = (float*)d_out;
    float* rel_out = out_f;
    float* v_out   = out_f + (size_t)Ne * Dm;

    float* Xv   = getsym(g_Xv);
    float* vj   = getsym(g_vj);
    float* SOQQ = getsym(g_SOQQ);
    float* QQ2  = getsym(g_QQ2);
    float* Xr   = getsym(g_Xr);
    float* rj   = getsym(g_rj);
    float* relj = getsym(g_relj);
    float* XrcB = getsym(g_Xrc2);
    float* Xc   = getsym(g_Xc);
    float* Xn   = getsym(g_Xn);
    float* part = getsym(g_part);
    float* WjA  = getsym(g_WjA);
    float* WjB  = getsym(g_WjB);
    float* WrA  = getsym(g_WrA);
    float* WrB  = getsym(g_WrB);
    float* xrc[2] = {XrcB, XrcB + (size_t)Ne * 2048};

    k_setup<<<512, 256>>>(v, rel, eidx, xrc[0]);
    k_wcomb<<<4096, 256>>>(W_joint, W_reljnt);

    for (int t = 0; t < 2; ++t) {
        int Kx = (t == 0) ? 2048 : 3072;        // folded-K for vj/rj
        const float* Wj = (t == 0) ? WjA : WjB;
        const float* Wr = (t == 0) ? WrA : WrB;

        // vj = Xv @ Wj^T   (M=64, split-K 16)
        k_gemm<<<dim3(8, 1, 16), 128>>>(Xv, Kx, Wj, Wj, Wj, Wj,
                                        Kx, Kx, part, 1024, 65536, Kx / 16);
        k_reduce<<<256, 256>>>(part, vj, 65536, 16, nullptr, 0, nullptr);

        // rj = Xr @ Wr^T  (tensor, folded K)
        k_tgemm<0><<<dim3(16, 8), 256>>>(Xr, Kx, Wr, Kx, rj, Kx,
                                         nullptr, nullptr, 0);

        // node batch: SOQQ = vj @ [Ws | Wo | W_sub | W_obj]^T  (N=4096, split-K 8)
        k_gemm<<<dim3(32, 1, 8), 128>>>(vj, 1024, W_relup, W_relup + 1024, W_sub, W_obj,
                                        3072, 1024, part, 4096, 262144, 128);
        k_reduce<<<1024, 256>>>(part, SOQQ, 262144, 8, nullptr, 0, nullptr);

        // relj = S[src] + O[dst] + rj @ Wr3^T  (tensor, K=1024, epi -> xrc[t] 2nd half)
        k_tgemm<1><<<dim3(16, 8), 256>>>(rj, 1024, W_relup + 2048, 3072, relj, 1024,
                                         xrc[t], nullptr, 0);

        // QQ2 = [Qs @ W_r2s | Qo @ W_r2o]  (NN, N=2048, split-K 8)
        k_gemmNN<<<dim3(16, 1, 8), 128>>>(SOQQ + 2048, SOQQ + 3072, 4096,
                                          W_r2s, W_r2o, 1024,
                                          part, 2048, 131072, 128);
        k_reduce<<<512, 256>>>(part, QQ2, 131072, 8, nullptr, 0, nullptr);

        // scores, softmax, aggregation
        k_score<<<Ne, 128>>>();
        k_softmax<<<1, 128>>>(conn);
        k_ctx<<<dim3(64, 2), 256>>>(conn);

        // vctx = Xc @ W_ctx^T  (M=64, K=3072, split-K 16; reduce builds Xc/Xv/Xn)
        k_gemm<<<dim3(8, 1, 16), 128>>>(Xc, 3072, W_ctx, W_ctx, W_ctx, W_ctx,
                                        3072, 3072, part, 1024, 65536, 192);
        k_reduce<<<256, 256>>>(part, nullptr, 65536, 16, nullptr, 2, v);

        // relctx = xrc[t] @ W_rel_ctx^T  (tensor K=2048; epi -> xrc[t^1] (+Xr) or final)
        k_tgemm<2><<<dim3(16, 8), 256>>>(xrc[t], 2048, W_relctx, 2048, nullptr, 2048,
                                         xrc[t ^ 1], rel, (t == 0) ? 1 : 2);
    }

    // rel_out = [rel, relctx] @ W_factor^T  (tensor K=2048)
    k_tgemm<0><<<dim3(16, 8), 256>>>(xrc[0], 2048, W_factor, 2048, rel_out, 2048,
                                     nullptr, nullptr, 0);

    // v_out = Xn @ W_node^T + b_node
    k_gemm<<<dim3(8, 1, 16), 128>>>(Xn, 2048, W_node, W_node, W_node, W_node,
                                    2048, 2048, part, 1024, 65536, 128);
    k_reduce<<<256, 256>>>(part, v_out, 65536, 16, b_node, 1, nullptr);
}

// round 7
// speedup vs baseline: 3.1248x; 1.7097x over previous
#include <cuda_runtime.h>
#include <cstdint>

#define Dm 1024
#define Nn 64
#define Ne 1024

// ---------------- scratch (device globals; no allocations allowed) ----------------
__device__ float g_Xv[Nn * 3 * Dm];      // t0: [v, v^2] ld2048; t1: [v,vctx,v*vctx] ld3072
__device__ float g_vj[Nn * Dm];
__device__ float g_SOQQ[Nn * 4 * Dm];    // [S | O | Qs | Qo], ldc 4096
__device__ float g_QQ2[Nn * 2 * Dm];     // [Qs2 | Qo2], ldc 2048
__device__ float g_Xr[Ne * 3 * Dm];      // t0: [rel, rel^2] ld2048; t1: [rel,ctx,rel*ctx] ld3072 (tf32-rounded)
__device__ float g_rj[Ne * Dm];          // tf32-rounded (A of relj gemm)
__device__ float g_relj[Ne * Dm];        // full f32 (score/ctx consumers)
__device__ float g_Xrc2[2 * Ne * 2 * Dm];  // ping-pong [relctx | relj], tf32-rounded (A-side)
__device__ float g_Xc[Nn * 3 * Dm];
__device__ float g_Xn[Nn * 2 * Dm];
__device__ float g_part[8 * Nn * 4 * Dm];
__device__ float g_WjA[Dm * 2048];       // [Wj1+Wj2 | Wj3]            (FFMA, exact)
__device__ float g_WjB[Dm * 3072];       // [Wj1-Wj4 | Wj2+Wj4 | Wj3]  (FFMA, exact)
__device__ float g_WrA[Dm * 2048];       // rj t0 B, tf32-rounded
__device__ float g_WrB[Dm * 3072];       // rj t1 B, tf32-rounded
__device__ float g_Wr3[Dm * Dm];         // W_relup 3rd slice, dense, tf32-rounded
__device__ float g_Wrc[Dm * 2048];       // W_relctx, tf32-rounded
__device__ float g_Wf[Dm * 2048];        // W_factor, tf32-rounded
__device__ float g_ssbj[Ne];
__device__ float g_sobj[Ne];
__device__ float g_wsbj[Ne];
__device__ float g_wobj[Ne];
__device__ int g_src[Ne];
__device__ int g_dst[Ne];

__device__ __forceinline__ uint32_t f2tf32(float x) {
    uint32_t u;
    asm("cvt.rna.tf32.f32 %0, %1;" : "=r"(u) : "f"(x));
    return u;
}
__device__ __forceinline__ float rtf(float x) { return __uint_as_float(f2tf32(x)); }

__device__ __forceinline__ uint32_t smem_u32(const void* p) {
    uint32_t r;
    asm("{ .reg .u64 t; cvta.to.shared.u64 t, %1; cvt.u32.u64 %0, t; }" : "=r"(r) : "l"(p));
    return r;
}

// ---------------- weight folding + tensor-B rounding ----------------
// vj input is [a, c, a*c, c-a]  ->  a@(W1-W4) + c@(W2+W4) + (a*c)@W3   (FFMA, exact)
// rj input is [r, c, r*c, r-c]  ->  r@(W1+W4) + c@(W2-W4) + (r*c)@W3   (tensor, rounded)
__global__ void k_wcomb(const float* __restrict__ Wj, const float* __restrict__ Wr,
                        const float* __restrict__ Wrelup, const float* __restrict__ Wrelctx,
                        const float* __restrict__ Wfactor) {
    int idx = blockIdx.x * 256 + threadIdx.x;
    if (idx >= Dm * Dm) return;
    int o = idx >> 10, d = idx & 1023;
    {
        const float* r = Wj + (size_t)o * 4096;
        float w1 = r[d], w2 = r[1024 + d], w3 = r[2048 + d], w4 = r[3072 + d];
        g_WjA[(size_t)o * 2048 + d] = w1 + w2;
        g_WjA[(size_t)o * 2048 + 1024 + d] = w3;
        g_WjB[(size_t)o * 3072 + d] = w1 - w4;
        g_WjB[(size_t)o * 3072 + 1024 + d] = w2 + w4;
        g_WjB[(size_t)o * 3072 + 2048 + d] = w3;
    }
    {
        const float* r = Wr + (size_t)o * 4096;
        float w1 = r[d], w2 = r[1024 + d], w3 = r[2048 + d], w4 = r[3072 + d];
        g_WrA[(size_t)o * 2048 + d] = rtf(w1 + w2);
        g_WrA[(size_t)o * 2048 + 1024 + d] = rtf(w3);
        g_WrB[(size_t)o * 3072 + d] = rtf(w1 + w4);
        g_WrB[(size_t)o * 3072 + 1024 + d] = rtf(w2 - w4);
        g_WrB[(size_t)o * 3072 + 2048 + d] = rtf(w3);
    }
    g_Wr3[(size_t)o * 1024 + d] = rtf(Wrelup[(size_t)o * 3072 + 2048 + d]);
    g_Wrc[(size_t)o * 2048 + d] = rtf(Wrelctx[(size_t)o * 2048 + d]);
    g_Wrc[(size_t)o * 2048 + 1024 + d] = rtf(Wrelctx[(size_t)o * 2048 + 1024 + d]);
    g_Wf[(size_t)o * 2048 + d] = rtf(Wfactor[(size_t)o * 2048 + d]);
    g_Wf[(size_t)o * 2048 + 1024 + d] = rtf(Wfactor[(size_t)o * 2048 + 1024 + d]);
}

// ---------------- setup ----------------
__global__ void k_setup(const float* __restrict__ v, const float* __restrict__ rel,
                        const int* __restrict__ eidx, float* __restrict__ xrcA) {
    int i0 = blockIdx.x * blockDim.x + threadIdx.x;
    int stride = gridDim.x * blockDim.x;
    for (int t = i0; t < Ne * Dm; t += stride) {
        int e = t >> 10, d = t & 1023;
        float r = rel[t];
        float* xr = g_Xr + (size_t)e * 2048;
        xr[d] = rtf(r); xr[1024 + d] = rtf(r * r);
        xrcA[(size_t)e * 2048 + d] = rtf(r);
    }
    for (int t = i0; t < Nn * Dm; t += stride) {
        int i = t >> 10, d = t & 1023;
        float a = v[t];
        float* xv = g_Xv + (size_t)i * 2048;
        xv[d] = a; xv[1024 + d] = a * a;
        g_Xc[(size_t)i * 3072 + d] = a;
    }
    for (int t = i0; t < Ne; t += stride) {
        int e = eidx[t];
        g_src[t] = e >> 6;
        g_dst[t] = e & 63;
    }
}

// ======================= tf32 tensor-core NT GEMM (cp.async 3-stage) ==========
// C[M,1024] = A[M,K] * B[1024,K]^T, BM=128 BN=64 BK=16, 256 thr, 8 warps 32x32.
// Inputs are PRE-ROUNDED to tf32 (valid f32 bit patterns); no cvt in kernel.
// MODE 0: write C (f32).  MODE 3: write C rounded (rj -> A of next gemm).
// MODE 1: C += SOQQ[src]+SOQQ[dst+1024] (f32); xrc 2nd half rounded.
// MODE 2: no C; flag==1 -> xrc relctx + Xr=[rel,ctx,rel*ctx] all rounded (ld 3072);
//         flag==2 -> final xrc=[rel, relctx] rounded.
#define TS 3
#define APAD 20

template <int MODE>
__global__ void __launch_bounds__(256) k_tgemm(
    const float* __restrict__ A, int lda,
    const float* __restrict__ B, int ldb,
    float* __restrict__ C, int K,
    float* __restrict__ xrc_w, const float* __restrict__ rel, int flag) {
    __shared__ float As[TS][128][APAD];   // 30720 B
    __shared__ float Bs[TS][64][APAD];    // 15360 B

    int tid = threadIdx.x;
    int lane = tid & 31;
    int w = tid >> 5;
    int wm = (w & 3) * 32;
    int wn = (w >> 2) * 32;
    int gr = lane >> 2;
    int gc = lane & 3;

    // cp.async copy mapping: A 128 rows x 64B -> 2x16B per thread; B 64 rows x 64B -> 1x16B
    const float* Ag = A + (size_t)(blockIdx.y * 128 + (tid >> 1)) * lda + (tid & 1) * 8;
    const float* Bg = B + (size_t)(blockIdx.x * 64 + (tid >> 2)) * ldb + (tid & 3) * 4;
    uint32_t a_dst = smem_u32(&As[0][tid >> 1][(tid & 1) * 8]);
    uint32_t b_dst = smem_u32(&Bs[0][tid >> 2][(tid & 3) * 4]);
    const uint32_t A_STAGE = 128 * APAD * 4;
    const uint32_t B_STAGE = 64 * APAD * 4;

    int niter = K >> 4;

#define ISSUE_STAGE(s, k0)                                                              \
    do {                                                                                \
        uint32_t ad = a_dst + (uint32_t)(s) * A_STAGE;                                  \
        const float* ap = Ag + (k0);                                                    \
        asm volatile("cp.async.cg.shared.global [%0], [%1], 16;" :: "r"(ad), "l"(ap));  \
        asm volatile("cp.async.cg.shared.global [%0], [%1], 16;" :: "r"(ad + 16), "l"(ap + 4)); \
        uint32_t bd = b_dst + (uint32_t)(s) * B_STAGE;                                  \
        const float* bp = Bg + (k0);                                                    \
        asm volatile("cp.async.cg.shared.global [%0], [%1], 16;" :: "r"(bd), "l"(bp));  \
    } while (0)

    ISSUE_STAGE(0, 0);
    asm volatile("cp.async.commit_group;");
    ISSUE_STAGE(1, 16);
    asm volatile("cp.async.commit_group;");

    float c[2][4][4];
#pragma unroll
    for (int mt = 0; mt < 2; ++mt)
#pragma unroll
        for (int nt = 0; nt < 4; ++nt)
#pragma unroll
            for (int q = 0; q < 4; ++q) c[mt][nt][q] = 0.f;

    const uint32_t* Asu = reinterpret_cast<const uint32_t*>(&As[0][0][0]);
    const uint32_t* Bsu = reinterpret_cast<const uint32_t*>(&Bs[0][0][0]);

    int s = 0;
    for (int i = 0; i < niter; ++i) {
        asm volatile("cp.async.wait_group 1;" ::: "memory");
        __syncthreads();
        {
            int nx = i + 2;
            if (nx < niter) {
                int sn = s + 2; if (sn >= TS) sn -= TS;
                ISSUE_STAGE(sn, nx * 16);
            }
            asm volatile("cp.async.commit_group;");
        }
        int base_a = s * 128 * APAD;
        int base_b = s * 64 * APAD;
#pragma unroll
        for (int ks = 0; ks < 2; ++ks) {
            int kb = ks * 8 + gc;
            uint32_t a[2][4], b[4][2];
#pragma unroll
            for (int mt = 0; mt < 2; ++mt) {
                int m0 = wm + mt * 16 + gr;
                a[mt][0] = Asu[base_a + m0 * APAD + kb];
                a[mt][1] = Asu[base_a + (m0 + 8) * APAD + kb];
                a[mt][2] = Asu[base_a + m0 * APAD + kb + 4];
                a[mt][3] = Asu[base_a + (m0 + 8) * APAD + kb + 4];
            }
#pragma unroll
            for (int nt = 0; nt < 4; ++nt) {
                int n0 = wn + nt * 8 + gr;
                b[nt][0] = Bsu[base_b + n0 * APAD + kb];
                b[nt][1] = Bsu[base_b + n0 * APAD + kb + 4];
            }
#pragma unroll
            for (int mt = 0; mt < 2; ++mt)
#pragma unroll
                for (int nt = 0; nt < 4; ++nt) {
                    asm volatile(
                        "mma.sync.aligned.m16n8k8.row.col.f32.tf32.tf32.f32 "
                        "{%0,%1,%2,%3}, {%4,%5,%6,%7}, {%8,%9}, {%0,%1,%2,%3};"
                        : "+f"(c[mt][nt][0]), "+f"(c[mt][nt][1]),
                          "+f"(c[mt][nt][2]), "+f"(c[mt][nt][3])
                        : "r"(a[mt][0]), "r"(a[mt][1]), "r"(a[mt][2]), "r"(a[mt][3]),
                          "r"(b[nt][0]), "r"(b[nt][1]));
                }
        }
        if (++s >= TS) s -= TS;
    }
#undef ISSUE_STAGE

    int mbase = blockIdx.y * 128 + wm;
    int nbase = blockIdx.x * 64 + wn;
#pragma unroll
    for (int mt = 0; mt < 2; ++mt) {
#pragma unroll
        for (int half = 0; half < 2; ++half) {
            int row = mbase + mt * 16 + gr + half * 8;
#pragma unroll
            for (int nt = 0; nt < 4; ++nt) {
                int col = nbase + nt * 8 + 2 * gc;
                float vx = c[mt][nt][half * 2 + 0];
                float vy = c[mt][nt][half * 2 + 1];
                if (MODE == 0) {
                    *(float2*)(C + (size_t)row * 1024 + col) = make_float2(vx, vy);
                } else if (MODE == 3) {
                    *(float2*)(C + (size_t)row * 1024 + col) = make_float2(rtf(vx), rtf(vy));
                } else if (MODE == 1) {
                    const float* sp = g_SOQQ + (size_t)g_src[row] * 4096 + col;
                    const float* op = g_SOQQ + (size_t)g_dst[row] * 4096 + 1024 + col;
                    vx += sp[0] + op[0];
                    vy += sp[1] + op[1];
                    *(float2*)(C + (size_t)row * 1024 + col) = make_float2(vx, vy);
                    *(float2*)(xrc_w + (size_t)row * 2048 + 1024 + col) =
                        make_float2(rtf(vx), rtf(vy));
                } else {  // MODE 2
                    float2 rv = *(const float2*)(rel + (size_t)row * 1024 + col);
                    if (flag == 1) {
                        *(float2*)(xrc_w + (size_t)row * 2048 + col) =
                            make_float2(rtf(vx), rtf(vy));
                        float* xr = g_Xr + (size_t)row * 3072;
                        *(float2*)(xr + col)        = make_float2(rtf(rv.x), rtf(rv.y));
                        *(float2*)(xr + 1024 + col) = make_float2(rtf(vx), rtf(vy));
                        *(float2*)(xr + 2048 + col) =
                            make_float2(rtf(rv.x * vx), rtf(rv.y * vy));
                    } else {
                        *(float2*)(xrc_w + (size_t)row * 2048 + col) =
                            make_float2(rtf(rv.x), rtf(rv.y));
                        *(float2*)(xrc_w + (size_t)row * 2048 + 1024 + col) =
                            make_float2(rtf(vx), rtf(vy));
                    }
                }
            }
        }
    }
}

// ---------------- FFMA NT GEMM, M=64, split-K, 4-region B select ----------------
__global__ void __launch_bounds__(128) k_gemm(
    const float* __restrict__ A, int lda,
    const float* __restrict__ B0, const float* __restrict__ B1,
    const float* __restrict__ B2, const float* __restrict__ B3,
    int ldb01, int ldb23,
    float* __restrict__ part, int ldc, size_t strideCz, int Kc) {
    __shared__ float As[16][64];
    __shared__ float Bs[16][128];
    int tid = threadIdx.x;
    int trow = tid >> 4;
    int tcol = tid & 15;
    int bx = blockIdx.x;
    int region = bx >> 3;
    const float* Bp = (region == 0) ? B0 : (region == 1) ? B1 : (region == 2) ? B2 : B3;
    int ldb = (region < 2) ? ldb01 : ldb23;
    const float* Ab = A + (size_t)blockIdx.z * Kc;
    const float* Bb = Bp + (size_t)((bx & 7) * 128) * ldb + (size_t)blockIdx.z * Kc;

    float acc[8][8];
#pragma unroll
    for (int i = 0; i < 8; ++i)
#pragma unroll
        for (int j = 0; j < 8; ++j) acc[i][j] = 0.f;

    for (int k0 = 0; k0 < Kc; k0 += 16) {
#pragma unroll
        for (int it = 0; it < 2; ++it) {
            int f = tid + it * 128;
            int r = f >> 2, q = f & 3;
            float4 vv = *(const float4*)(Ab + (size_t)r * lda + k0 + q * 4);
            As[q * 4 + 0][r] = vv.x; As[q * 4 + 1][r] = vv.y;
            As[q * 4 + 2][r] = vv.z; As[q * 4 + 3][r] = vv.w;
        }
#pragma unroll
        for (int it = 0; it < 4; ++it) {
            int f = tid + it * 128;
            int r = f >> 2, q = f & 3;
            float4 vv = *(const float4*)(Bb + (size_t)r * ldb + k0 + q * 4);
            Bs[q * 4 + 0][r] = vv.x; Bs[q * 4 + 1][r] = vv.y;
            Bs[q * 4 + 2][r] = vv.z; Bs[q * 4 + 3][r] = vv.w;
        }
        __syncthreads();
#pragma unroll
        for (int kk = 0; kk < 16; ++kk) {
            float a[8], b[8];
            *(float4*)(a)     = *(const float4*)&As[kk][trow * 8];
            *(float4*)(a + 4) = *(const float4*)&As[kk][trow * 8 + 4];
            *(float4*)(b)     = *(const float4*)&Bs[kk][tcol * 8];
            *(float4*)(b + 4) = *(const float4*)&Bs[kk][tcol * 8 + 4];
#pragma unroll
            for (int i = 0; i < 8; ++i)
#pragma unroll
                for (int j = 0; j < 8; ++j) acc[i][j] += a[i] * b[j];
        }
        __syncthreads();
    }

    float* Cz = part + (size_t)blockIdx.z * strideCz;
    int m0 = trow * 8;
    int n0g = bx * 128 + tcol * 8;
#pragma unroll
    for (int i = 0; i < 8; ++i) {
        float* crow = Cz + (size_t)(m0 + i) * ldc + n0g;
        *(float4*)(crow)     = make_float4(acc[i][0], acc[i][1], acc[i][2], acc[i][3]);
        *(float4*)(crow + 4) = make_float4(acc[i][4], acc[i][5], acc[i][6], acc[i][7]);
    }
}

// ---------------- FFMA NN GEMM, M=64, split-K, 2-region A/B select ----------------
__global__ void __launch_bounds__(128) k_gemmNN(
    const float* __restrict__ A0, const float* __restrict__ A1, int lda,
    const float* __restrict__ B0, const float* __restrict__ B1, int ldb,
    float* __restrict__ part, int ldc, size_t strideCz, int Kc) {
    __shared__ float As[16][64];
    __shared__ float Bs[16][128];
    int tid = threadIdx.x;
    int trow = tid >> 4;
    int tcol = tid & 15;
    int bx = blockIdx.x;
    int region = bx >> 3;
    const float* A = region ? A1 : A0;
    const float* B = region ? B1 : B0;
    int nl = (bx & 7) * 128;
    int kbase = blockIdx.z * Kc;

    float acc[8][8];
#pragma unroll
    for (int i = 0; i < 8; ++i)
#pragma unroll
        for (int j = 0; j < 8; ++j) acc[i][j] = 0.f;

    for (int k0 = 0; k0 < Kc; k0 += 16) {
#pragma unroll
        for (int it = 0; it < 2; ++it) {
            int f = tid + it * 128;
            int m = f >> 2, q = f & 3;
            float4 av = *(const float4*)(A + (size_t)m * lda + kbase + k0 + q * 4);
            As[q * 4 + 0][m] = av.x; As[q * 4 + 1][m] = av.y;
            As[q * 4 + 2][m] = av.z; As[q * 4 + 3][m] = av.w;
        }
#pragma unroll
        for (int it = 0; it < 4; ++it) {
            int f = tid + it * 128;
            int k = f >> 5, n4 = f & 31;
            *(float4*)&Bs[k][n4 * 4] =
                *(const float4*)(B + (size_t)(kbase + k0 + k) * ldb + nl + n4 * 4);
        }
        __syncthreads();
#pragma unroll
        for (int kk = 0; kk < 16; ++kk) {
            float a[8], b[8];
            *(float4*)(a)     = *(const float4*)&As[kk][trow * 8];
            *(float4*)(a + 4) = *(const float4*)&As[kk][trow * 8 + 4];
            *(float4*)(b)     = *(const float4*)&Bs[kk][tcol * 8];
            *(float4*)(b + 4) = *(const float4*)&Bs[kk][tcol * 8 + 4];
#pragma unroll
            for (int i = 0; i < 8; ++i)
#pragma unroll
                for (int j = 0; j < 8; ++j) acc[i][j] += a[i] * b[j];
        }
        __syncthreads();
    }

    float* Cz = part + (size_t)blockIdx.z * strideCz;
    int m0 = trow * 8;
    int n0g = bx * 128 + tcol * 8;
#pragma unroll
    for (int i = 0; i < 8; ++i) {
        float* crow = Cz + (size_t)(m0 + i) * ldc + n0g;
        *(float4*)(crow)     = make_float4(acc[i][0], acc[i][1], acc[i][2], acc[i][3]);
        *(float4*)(crow + 4) = make_float4(acc[i][4], acc[i][5], acc[i][6], acc[i][7]);
    }
}

// split-K reduce. mode 0: plain. 1: +bias. 2: vctx epilogue (builds Xc/Xv/Xn).
__global__ void k_reduce(const float* __restrict__ part, float* __restrict__ C,
                         int total, int splitk, const float* __restrict__ bias,
                         int mode, const float* __restrict__ v) {
    int idx = blockIdx.x * 256 + threadIdx.x;
    if (idx >= total) return;
    float s = 0.f;
    for (int z = 0; z < splitk; ++z) s += part[(size_t)z * total + idx];
    if (mode == 2) {
        int m = idx >> 10, d = idx & 1023;
        float a = v[idx];
        g_Xc[(size_t)m * 3072 + d] = s;
        float* xv = g_Xv + (size_t)m * 3072;
        xv[d] = a; xv[1024 + d] = s; xv[2048 + d] = a * s;
        float* xn = g_Xn + (size_t)m * 2048;
        xn[d] = a; xn[1024 + d] = s;
    } else {
        if (mode == 1) s += bias[idx & 1023];
        C[idx] = s;
    }
}

// ---------------- per-edge attention scores ----------------
__global__ void k_score() {
    int e = blockIdx.x;
    int tid = threadIdx.x;  // 128
    const float* qs = g_QQ2 + (size_t)g_src[e] * 2048;
    const float* qo = g_QQ2 + (size_t)g_dst[e] * 2048 + 1024;
    const float* rj = g_relj + (size_t)e * Dm;
    float a1 = 0.f, a2 = 0.f;
    for (int d = tid; d < Dm; d += 128) {
        float r = rj[d];
        a1 += qs[d] * r;
        a2 += qo[d] * r;
    }
#pragma unroll
    for (int off = 16; off; off >>= 1) {
        a1 += __shfl_down_sync(0xffffffffu, a1, off);
        a2 += __shfl_down_sync(0xffffffffu, a2, off);
    }
    __shared__ float sh1[4], sh2[4];
    if ((tid & 31) == 0) { sh1[tid >> 5] = a1; sh2[tid >> 5] = a2; }
    __syncthreads();
    if (tid == 0) {
        g_ssbj[e] = (sh1[0] + sh1[1] + sh1[2] + sh1[3]) * (1.f / 32.f);
        g_sobj[e] = (sh2[0] + sh2[1] + sh2[2] + sh2[3]) * (1.f / 32.f);
    }
}

// ---------------- masked softmax ----------------
__global__ void k_softmax(const int* __restrict__ conn) {
    int tid = threadIdx.x;  // 128
    float ex[64];
    if (tid < 64) {
        int i = tid;
        float m = -1e30f;
        for (int j = 0; j < 64; ++j) {
            int k = conn[i * 64 + j];
            if (k >= 0) m = fmaxf(m, g_ssbj[k]);
        }
        float sum = 0.f;
        for (int j = 0; j < 64; ++j) {
            int k = conn[i * 64 + j];
            float e = (k >= 0) ? expf(g_ssbj[k] - m) : 0.f;
            ex[j] = e; sum += e;
        }
        float inv = 1.f / sum;
        for (int j = 0; j < 64; ++j) {
            int k = conn[i * 64 + j];
            if (k >= 0) g_wsbj[k] = ex[j] * inv;
        }
    } else {
        int j = tid - 64;
        float m = -1e30f;
        for (int i = 0; i < 64; ++i) {
            int k = conn[i * 64 + j];
            if (k >= 0) m = fmaxf(m, g_sobj[k]);
        }
        float sum = 0.f;
        for (int i = 0; i < 64; ++i) {
            int k = conn[i * 64 + j];
            float e = (k >= 0) ? expf(g_sobj[k] - m) : 0.f;
            ex[i] = e; sum += e;
        }
        float inv = 1.f / sum;
        for (int i = 0; i < 64; ++i) {
            int k = conn[i * 64 + j];
            if (k >= 0) g_wobj[k] = ex[i] * inv;
        }
    }
}

// ---------------- ctx aggregation -> Xc cols 1024+/2048+ ----------------
__global__ void k_ctx(const int* __restrict__ conn) {
    int tid = threadIdx.x;  // 256
    if (blockIdx.y == 0) {
        int i = blockIdx.x;
#pragma unroll
        for (int dd = 0; dd < 4; ++dd) {
            int d = tid + dd * 256;
            float acc = 0.f;
            for (int j = 0; j < 64; ++j) {
                int k = conn[i * 64 + j];
                if (k >= 0) acc += g_wsbj[k] * g_relj[(size_t)k * Dm + d];
            }
            g_Xc[(size_t)i * 3072 + 1024 + d] = acc;
        }
    } else {
        int j = blockIdx.x;
#pragma unroll
        for (int dd = 0; dd < 4; ++dd) {
            int d = tid + dd * 256;
            float acc = 0.f;
            for (int i = 0; i < 64; ++i) {
                int k = conn[i * 64 + j];
                if (k >= 0) acc += g_wobj[k] * g_relj[(size_t)k * Dm + d];
            }
            g_Xc[(size_t)j * 3072 + 2048 + d] = acc;
        }
    }
}

// ---------------- host side ----------------
static float* getsym(const void* s) {
    void* p = nullptr;
    cudaGetSymbolAddress(&p, s);
    return (float*)p;
}

extern "C" void kernel_launch(void* const* d_in, const int* in_sizes, int n_in,
                              void* d_out, int out_size) {
    (void)in_sizes; (void)n_in; (void)out_size;
    const float* v        = (const float*)d_in[0];
    const float* rel      = (const float*)d_in[1];
    const int*   conn     = (const int*)d_in[2];
    const int*   eidx     = (const int*)d_in[4];
    const float* W_sub    = (const float*)d_in[5];
    const float* W_obj    = (const float*)d_in[6];
    const float* W_r2s    = (const float*)d_in[7];
    const float* W_r2o    = (const float*)d_in[8];
    const float* W_joint  = (const float*)d_in[9];
    const float* W_ctx    = (const float*)d_in[10];
    const float* W_relup  = (const float*)d_in[11];
    const float* W_reljnt = (const float*)d_in[12];
    const float* W_relctx = (const float*)d_in[13];
    const float* W_node   = (const float*)d_in[14];
    const float* b_node   = (const float*)d_in[15];
    const float* W_factor = (const float*)d_in[16];

    float* out_f   = (float*)d_out;
    float* rel_out = out_f;
    float* v_out   = out_f + (size_t)Ne * Dm;

    float* Xv   = getsym(g_Xv);
    float* vj   = getsym(g_vj);
    float* SOQQ = getsym(g_SOQQ);
    float* QQ2  = getsym(g_QQ2);
    float* Xr   = getsym(g_Xr);
    float* rj   = getsym(g_rj);
    float* relj = getsym(g_relj);
    float* XrcB = getsym(g_Xrc2);
    float* Xc   = getsym(g_Xc);
    float* Xn   = getsym(g_Xn);
    float* part = getsym(g_part);
    float* WjA  = getsym(g_WjA);
    float* WjB  = getsym(g_WjB);
    float* WrA  = getsym(g_WrA);
    float* WrB  = getsym(g_WrB);
    float* Wr3  = getsym(g_Wr3);
    float* Wrc  = getsym(g_Wrc);
    float* Wf   = getsym(g_Wf);
    float* xrc[2] = {XrcB, XrcB + (size_t)Ne * 2048};

    k_setup<<<512, 256>>>(v, rel, eidx, xrc[0]);
    k_wcomb<<<4096, 256>>>(W_joint, W_reljnt, W_relup, W_relctx, W_factor);

    for (int t = 0; t < 2; ++t) {
        int Kx = (t == 0) ? 2048 : 3072;        // folded-K for vj/rj
        const float* Wj = (t == 0) ? WjA : WjB;
        const float* Wr = (t == 0) ? WrA : WrB;

        // vj = Xv @ Wj^T   (M=64, split-K 16, FFMA)
        k_gemm<<<dim3(8, 1, 16), 128>>>(Xv, Kx, Wj, Wj, Wj, Wj,
                                        Kx, Kx, part, 1024, 65536, Kx / 16);
        k_reduce<<<256, 256>>>(part, vj, 65536, 16, nullptr, 0, nullptr);

        // rj = Xr @ Wr^T  (tensor, folded K, rounded output)
        k_tgemm<3><<<dim3(16, 8), 256>>>(Xr, Kx, Wr, Kx, rj, Kx,
                                         nullptr, nullptr, 0);

        // node batch: SOQQ = vj @ [Ws | Wo | W_sub | W_obj]^T  (N=4096, split-K 8)
        k_gemm<<<dim3(32, 1, 8), 128>>>(vj, 1024, W_relup, W_relup + 1024, W_sub, W_obj,
                                        3072, 1024, part, 4096, 262144, 128);
        k_reduce<<<1024, 256>>>(part, SOQQ, 262144, 8, nullptr, 0, nullptr);

        // relj = S[src] + O[dst] + rj @ Wr3^T  (tensor, K=1024, epi -> xrc[t] 2nd half)
        k_tgemm<1><<<dim3(16, 8), 256>>>(rj, 1024, Wr3, 1024, relj, 1024,
                                         xrc[t], nullptr, 0);

        // QQ2 = [Qs @ W_r2s | Qo @ W_r2o]  (NN, N=2048, split-K 8)
        k_gemmNN<<<dim3(16, 1, 8), 128>>>(SOQQ + 2048, SOQQ + 3072, 4096,
                                          W_r2s, W_r2o, 1024,
                                          part, 2048, 131072, 128);
        k_reduce<<<512, 256>>>(part, QQ2, 131072, 8, nullptr, 0, nullptr);

        // scores, softmax, aggregation
        k_score<<<Ne, 128>>>();
        k_softmax<<<1, 128>>>(conn);
        k_ctx<<<dim3(64, 2), 256>>>(conn);

        // vctx = Xc @ W_ctx^T  (M=64, K=3072, split-K 16; reduce builds Xc/Xv/Xn)
        k_gemm<<<dim3(8, 1, 16), 128>>>(Xc, 3072, W_ctx, W_ctx, W_ctx, W_ctx,
                                        3072, 3072, part, 1024, 65536, 192);
        k_reduce<<<256, 256>>>(part, nullptr, 65536, 16, nullptr, 2, v);

        // relctx = xrc[t] @ Wrc^T  (tensor K=2048; epi -> xrc[t^1] (+Xr) or final)
        k_tgemm<2><<<dim3(16, 8), 256>>>(xrc[t], 2048, Wrc, 2048, nullptr, 2048,
                                         xrc[t ^ 1], rel, (t == 0) ? 1 : 2);
    }

    // rel_out = [rel, relctx] @ Wf^T  (tensor K=2048)
    k_tgemm<0><<<dim3(16, 8), 256>>>(xrc[0], 2048, Wf, 2048, rel_out, 2048,
                                     nullptr, nullptr, 0);

    // v_out = Xn @ W_node^T + b_node
    k_gemm<<<dim3(8, 1, 16), 128>>>(Xn, 2048, W_node, W_node, W_node, W_node,
                                    2048, 2048, part, 1024, 65536, 128);
    k_reduce<<<256, 256>>>(part, v_out, 65536, 16, b_node, 1, nullptr);
}

// round 8
// speedup vs baseline: 3.2821x; 1.0503x over previous
#include <cuda_runtime.h>
#include <cstdint>

#define Dm 1024
#define Nn 64
#define Ne 1024

// ---------------- scratch (device globals; no allocations allowed) ----------------
__device__ float g_Xv[Nn * 3 * Dm];      // t0: [v, v^2] ld2048; t1: [v,vctx,v*vctx] ld3072
__device__ float g_vj[Nn * Dm];
__device__ float g_SOQQ[Nn * 4 * Dm];    // [S | O | Qs | Qo], ldc 4096
__device__ float g_QQ2[Nn * 2 * Dm];     // [Qs2 | Qo2], ldc 2048
__device__ float g_Xr[Ne * 3 * Dm];      // tf32-rounded A of rj gemm
__device__ float g_rj[Ne * Dm];          // tf32-rounded (A of relj gemm)
__device__ float g_relj[Ne * Dm];        // full f32 (attn consumer)
__device__ float g_Xrc2[2 * Ne * 2 * Dm];  // ping-pong [relctx | relj], tf32-rounded
__device__ float g_Xc[Nn * 3 * Dm];
__device__ float g_Xn[Nn * 2 * Dm];
__device__ float g_part[8 * Nn * 4 * Dm];
__device__ float g_WjA[Dm * 2048];       // [Wj1+Wj2 | Wj3]            (FFMA, exact)
__device__ float g_WjB[Dm * 3072];       // [Wj1-Wj4 | Wj2+Wj4 | Wj3]  (FFMA, exact)
__device__ float g_WrA[Dm * 2048];       // rj t0 B, tf32-rounded
__device__ float g_WrB[Dm * 3072];       // rj t1 B, tf32-rounded
__device__ float g_Wr3[Dm * Dm];         // W_relup 3rd slice, tf32-rounded
__device__ float g_Wrc[Dm * 2048];       // W_relctx, tf32-rounded
__device__ float g_Wf[Dm * 2048];        // W_factor, tf32-rounded
__device__ int g_src[Ne];
__device__ int g_dst[Ne];

__device__ __forceinline__ uint32_t f2tf32(float x) {
    uint32_t u;
    asm("cvt.rna.tf32.f32 %0, %1;" : "=r"(u) : "f"(x));
    return u;
}
__device__ __forceinline__ float rtf(float x) { return __uint_as_float(f2tf32(x)); }

__device__ __forceinline__ uint32_t smem_u32(const void* p) {
    uint32_t r;
    asm("{ .reg .u64 t; cvta.to.shared.u64 t, %1; cvt.u32.u64 %0, t; }" : "=r"(r) : "l"(p));
    return r;
}

// ---------------- weight folding + tensor-B rounding ----------------
__global__ void k_wcomb(const float* __restrict__ Wj, const float* __restrict__ Wr,
                        const float* __restrict__ Wrelup, const float* __restrict__ Wrelctx,
                        const float* __restrict__ Wfactor) {
    int idx = blockIdx.x * 256 + threadIdx.x;
    if (idx >= Dm * Dm) return;
    int o = idx >> 10, d = idx & 1023;
    {
        const float* r = Wj + (size_t)o * 4096;
        float w1 = r[d], w2 = r[1024 + d], w3 = r[2048 + d], w4 = r[3072 + d];
        g_WjA[(size_t)o * 2048 + d] = w1 + w2;
        g_WjA[(size_t)o * 2048 + 1024 + d] = w3;
        g_WjB[(size_t)o * 3072 + d] = w1 - w4;
        g_WjB[(size_t)o * 3072 + 1024 + d] = w2 + w4;
        g_WjB[(size_t)o * 3072 + 2048 + d] = w3;
    }
    {
        const float* r = Wr + (size_t)o * 4096;
        float w1 = r[d], w2 = r[1024 + d], w3 = r[2048 + d], w4 = r[3072 + d];
        g_WrA[(size_t)o * 2048 + d] = rtf(w1 + w2);
        g_WrA[(size_t)o * 2048 + 1024 + d] = rtf(w3);
        g_WrB[(size_t)o * 3072 + d] = rtf(w1 + w4);
        g_WrB[(size_t)o * 3072 + 1024 + d] = rtf(w2 - w4);
        g_WrB[(size_t)o * 3072 + 2048 + d] = rtf(w3);
    }
    g_Wr3[(size_t)o * 1024 + d] = rtf(Wrelup[(size_t)o * 3072 + 2048 + d]);
    g_Wrc[(size_t)o * 2048 + d] = rtf(Wrelctx[(size_t)o * 2048 + d]);
    g_Wrc[(size_t)o * 2048 + 1024 + d] = rtf(Wrelctx[(size_t)o * 2048 + 1024 + d]);
    g_Wf[(size_t)o * 2048 + d] = rtf(Wfactor[(size_t)o * 2048 + d]);
    g_Wf[(size_t)o * 2048 + 1024 + d] = rtf(Wfactor[(size_t)o * 2048 + 1024 + d]);
}

// ---------------- setup ----------------
__global__ void k_setup(const float* __restrict__ v, const float* __restrict__ rel,
                        const int* __restrict__ eidx, float* __restrict__ xrcA) {
    int i0 = blockIdx.x * blockDim.x + threadIdx.x;
    int stride = gridDim.x * blockDim.x;
    for (int t = i0; t < Ne * Dm; t += stride) {
        int e = t >> 10, d = t & 1023;
        float r = rel[t];
        float* xr = g_Xr + (size_t)e * 2048;
        xr[d] = rtf(r); xr[1024 + d] = rtf(r * r);
        xrcA[(size_t)e * 2048 + d] = rtf(r);
    }
    for (int t = i0; t < Nn * Dm; t += stride) {
        int i = t >> 10, d = t & 1023;
        float a = v[t];
        float* xv = g_Xv + (size_t)i * 2048;
        xv[d] = a; xv[1024 + d] = a * a;
        g_Xc[(size_t)i * 3072 + d] = a;
    }
    for (int t = i0; t < Ne; t += stride) {
        int e = eidx[t];
        g_src[t] = e >> 6;
        g_dst[t] = e & 63;
    }
}

// ======================= tf32 tensor-core NT GEMM (cp.async 3-stage) ==========
// C[M,1024] = A[M,K] * B[1024,K]^T, BM=128 BN=64 BK=16, 256 thr, 8 warps 32x32.
// Inputs PRE-ROUNDED to tf32. Fragments for BOTH k-groups prefetched before MMAs.
// MODE 0: write C (f32).  MODE 3: write C rounded.
// MODE 1: C += SOQQ[src]+SOQQ[dst+1024] (f32); xrc 2nd half rounded.
// MODE 2: no C; flag==1 -> xrc relctx + Xr=[rel,ctx,rel*ctx] rounded (ld 3072);
//         flag==2 -> final xrc=[rel, relctx] rounded.
#define TS 3
#define APAD 20

template <int MODE>
__global__ void __launch_bounds__(256) k_tgemm(
    const float* __restrict__ A, int lda,
    const float* __restrict__ B, int ldb,
    float* __restrict__ C, int K,
    float* __restrict__ xrc_w, const float* __restrict__ rel, int flag) {
    __shared__ float As[TS][128][APAD];   // 30720 B
    __shared__ float Bs[TS][64][APAD];    // 15360 B

    int tid = threadIdx.x;
    int lane = tid & 31;
    int w = tid >> 5;
    int wm = (w & 3) * 32;
    int wn = (w >> 2) * 32;
    int gr = lane >> 2;
    int gc = lane & 3;

    const float* Ag = A + (size_t)(blockIdx.y * 128 + (tid >> 1)) * lda + (tid & 1) * 8;
    const float* Bg = B + (size_t)(blockIdx.x * 64 + (tid >> 2)) * ldb + (tid & 3) * 4;
    uint32_t a_dst = smem_u32(&As[0][tid >> 1][(tid & 1) * 8]);
    uint32_t b_dst = smem_u32(&Bs[0][tid >> 2][(tid & 3) * 4]);
    const uint32_t A_STAGE = 128 * APAD * 4;
    const uint32_t B_STAGE = 64 * APAD * 4;

    int niter = K >> 4;

#define ISSUE_STAGE(s, k0)                                                              \
    do {                                                                                \
        uint32_t ad = a_dst + (uint32_t)(s) * A_STAGE;                                  \
        const float* ap = Ag + (k0);                                                    \
        asm volatile("cp.async.cg.shared.global [%0], [%1], 16;" :: "r"(ad), "l"(ap));  \
        asm volatile("cp.async.cg.shared.global [%0], [%1], 16;" :: "r"(ad + 16), "l"(ap + 4)); \
        uint32_t bd = b_dst + (uint32_t)(s) * B_STAGE;                                  \
        const float* bp = Bg + (k0);                                                    \
        asm volatile("cp.async.cg.shared.global [%0], [%1], 16;" :: "r"(bd), "l"(bp));  \
    } while (0)

    ISSUE_STAGE(0, 0);
    asm volatile("cp.async.commit_group;");
    ISSUE_STAGE(1, 16);
    asm volatile("cp.async.commit_group;");

    float c[2][4][4];
#pragma unroll
    for (int mt = 0; mt < 2; ++mt)
#pragma unroll
        for (int nt = 0; nt < 4; ++nt)
#pragma unroll
            for (int q = 0; q < 4; ++q) c[mt][nt][q] = 0.f;

    const uint32_t* Asu = reinterpret_cast<const uint32_t*>(&As[0][0][0]);
    const uint32_t* Bsu = reinterpret_cast<const uint32_t*>(&Bs[0][0][0]);

    int s = 0;
    for (int i = 0; i < niter; ++i) {
        asm volatile("cp.async.wait_group 1;" ::: "memory");
        __syncthreads();
        {
            int nx = i + 2;
            if (nx < niter) {
                int sn = s + 2; if (sn >= TS) sn -= TS;
                ISSUE_STAGE(sn, nx * 16);
            }
            asm volatile("cp.async.commit_group;");
        }
        int base_a = s * 128 * APAD;
        int base_b = s * 64 * APAD;
        // prefetch ALL fragments for both k-groups, then issue all MMAs
        uint32_t a[2][2][4], b[2][4][2];
#pragma unroll
        for (int ks = 0; ks < 2; ++ks) {
            int kb = ks * 8 + gc;
#pragma unroll
            for (int mt = 0; mt < 2; ++mt) {
                int m0 = wm + mt * 16 + gr;
                a[ks][mt][0] = Asu[base_a + m0 * APAD + kb];
                a[ks][mt][1] = Asu[base_a + (m0 + 8) * APAD + kb];
                a[ks][mt][2] = Asu[base_a + m0 * APAD + kb + 4];
                a[ks][mt][3] = Asu[base_a + (m0 + 8) * APAD + kb + 4];
            }
#pragma unroll
            for (int nt = 0; nt < 4; ++nt) {
                int n0 = wn + nt * 8 + gr;
                b[ks][nt][0] = Bsu[base_b + n0 * APAD + kb];
                b[ks][nt][1] = Bsu[base_b + n0 * APAD + kb + 4];
            }
        }
#pragma unroll
        for (int ks = 0; ks < 2; ++ks)
#pragma unroll
            for (int mt = 0; mt < 2; ++mt)
#pragma unroll
                for (int nt = 0; nt < 4; ++nt) {
                    asm volatile(
                        "mma.sync.aligned.m16n8k8.row.col.f32.tf32.tf32.f32 "
                        "{%0,%1,%2,%3}, {%4,%5,%6,%7}, {%8,%9}, {%0,%1,%2,%3};"
                        : "+f"(c[mt][nt][0]), "+f"(c[mt][nt][1]),
                          "+f"(c[mt][nt][2]), "+f"(c[mt][nt][3])
                        : "r"(a[ks][mt][0]), "r"(a[ks][mt][1]),
                          "r"(a[ks][mt][2]), "r"(a[ks][mt][3]),
                          "r"(b[ks][nt][0]), "r"(b[ks][nt][1]));
                }
        if (++s >= TS) s -= TS;
    }
#undef ISSUE_STAGE

    int mbase = blockIdx.y * 128 + wm;
    int nbase = blockIdx.x * 64 + wn;
#pragma unroll
    for (int mt = 0; mt < 2; ++mt) {
#pragma unroll
        for (int half = 0; half < 2; ++half) {
            int row = mbase + mt * 16 + gr + half * 8;
#pragma unroll
            for (int nt = 0; nt < 4; ++nt) {
                int col = nbase + nt * 8 + 2 * gc;
                float vx = c[mt][nt][half * 2 + 0];
                float vy = c[mt][nt][half * 2 + 1];
                if (MODE == 0) {
                    *(float2*)(C + (size_t)row * 1024 + col) = make_float2(vx, vy);
                } else if (MODE == 3) {
                    *(float2*)(C + (size_t)row * 1024 + col) = make_float2(rtf(vx), rtf(vy));
                } else if (MODE == 1) {
                    const float* sp = g_SOQQ + (size_t)g_src[row] * 4096 + col;
                    const float* op = g_SOQQ + (size_t)g_dst[row] * 4096 + 1024 + col;
                    vx += sp[0] + op[0];
                    vy += sp[1] + op[1];
                    *(float2*)(C + (size_t)row * 1024 + col) = make_float2(vx, vy);
                    *(float2*)(xrc_w + (size_t)row * 2048 + 1024 + col) =
                        make_float2(rtf(vx), rtf(vy));
                } else {  // MODE 2
                    float2 rv = *(const float2*)(rel + (size_t)row * 1024 + col);
                    if (flag == 1) {
                        *(float2*)(xrc_w + (size_t)row * 2048 + col) =
                            make_float2(rtf(vx), rtf(vy));
                        float* xr = g_Xr + (size_t)row * 3072;
                        *(float2*)(xr + col)        = make_float2(rtf(rv.x), rtf(rv.y));
                        *(float2*)(xr + 1024 + col) = make_float2(rtf(vx), rtf(vy));
                        *(float2*)(xr + 2048 + col) =
                            make_float2(rtf(rv.x * vx), rtf(rv.y * vy));
                    } else {
                        *(float2*)(xrc_w + (size_t)row * 2048 + col) =
                            make_float2(rtf(rv.x), rtf(rv.y));
                        *(float2*)(xrc_w + (size_t)row * 2048 + 1024 + col) =
                            make_float2(rtf(vx), rtf(vy));
                    }
                }
            }
        }
    }
}

// ---------------- FFMA NT GEMM, M=64, split-K, 4-region B select ----------------
__global__ void __launch_bounds__(128) k_gemm(
    const float* __restrict__ A, int lda,
    const float* __restrict__ B0, const float* __restrict__ B1,
    const float* __restrict__ B2, const float* __restrict__ B3,
    int ldb01, int ldb23,
    float* __restrict__ part, int ldc, size_t strideCz, int Kc) {
    __shared__ float As[16][64];
    __shared__ float Bs[16][128];
    int tid = threadIdx.x;
    int trow = tid >> 4;
    int tcol = tid & 15;
    int bx = blockIdx.x;
    int region = bx >> 3;
    const float* Bp = (region == 0) ? B0 : (region == 1) ? B1 : (region == 2) ? B2 : B3;
    int ldb = (region < 2) ? ldb01 : ldb23;
    const float* Ab = A + (size_t)blockIdx.z * Kc;
    const float* Bb = Bp + (size_t)((bx & 7) * 128) * ldb + (size_t)blockIdx.z * Kc;

    float acc[8][8];
#pragma unroll
    for (int i = 0; i < 8; ++i)
#pragma unroll
        for (int j = 0; j < 8; ++j) acc[i][j] = 0.f;

    for (int k0 = 0; k0 < Kc; k0 += 16) {
#pragma unroll
        for (int it = 0; it < 2; ++it) {
            int f = tid + it * 128;
            int r = f >> 2, q = f & 3;
            float4 vv = *(const float4*)(Ab + (size_t)r * lda + k0 + q * 4);
            As[q * 4 + 0][r] = vv.x; As[q * 4 + 1][r] = vv.y;
            As[q * 4 + 2][r] = vv.z; As[q * 4 + 3][r] = vv.w;
        }
#pragma unroll
        for (int it = 0; it < 4; ++it) {
            int f = tid + it * 128;
            int r = f >> 2, q = f & 3;
            float4 vv = *(const float4*)(Bb + (size_t)r * ldb + k0 + q * 4);
            Bs[q * 4 + 0][r] = vv.x; Bs[q * 4 + 1][r] = vv.y;
            Bs[q * 4 + 2][r] = vv.z; Bs[q * 4 + 3][r] = vv.w;
        }
        __syncthreads();
#pragma unroll
        for (int kk = 0; kk < 16; ++kk) {
            float a[8], b[8];
            *(float4*)(a)     = *(const float4*)&As[kk][trow * 8];
            *(float4*)(a + 4) = *(const float4*)&As[kk][trow * 8 + 4];
            *(float4*)(b)     = *(const float4*)&Bs[kk][tcol * 8];
            *(float4*)(b + 4) = *(const float4*)&Bs[kk][tcol * 8 + 4];
#pragma unroll
            for (int i = 0; i < 8; ++i)
#pragma unroll
                for (int j = 0; j < 8; ++j) acc[i][j] += a[i] * b[j];
        }
        __syncthreads();
    }

    float* Cz = part + (size_t)blockIdx.z * strideCz;
    int m0 = trow * 8;
    int n0g = bx * 128 + tcol * 8;
#pragma unroll
    for (int i = 0; i < 8; ++i) {
        float* crow = Cz + (size_t)(m0 + i) * ldc + n0g;
        *(float4*)(crow)     = make_float4(acc[i][0], acc[i][1], acc[i][2], acc[i][3]);
        *(float4*)(crow + 4) = make_float4(acc[i][4], acc[i][5], acc[i][6], acc[i][7]);
    }
}

// ---------------- FFMA NN GEMM, M=64, split-K, 2-region A/B select ----------------
__global__ void __launch_bounds__(128) k_gemmNN(
    const float* __restrict__ A0, const float* __restrict__ A1, int lda,
    const float* __restrict__ B0, const float* __restrict__ B1, int ldb,
    float* __restrict__ part, int ldc, size_t strideCz, int Kc) {
    __shared__ float As[16][64];
    __shared__ float Bs[16][128];
    int tid = threadIdx.x;
    int trow = tid >> 4;
    int tcol = tid & 15;
    int bx = blockIdx.x;
    int region = bx >> 3;
    const float* A = region ? A1 : A0;
    const float* B = region ? B1 : B0;
    int nl = (bx & 7) * 128;
    int kbase = blockIdx.z * Kc;

    float acc[8][8];
#pragma unroll
    for (int i = 0; i < 8; ++i)
#pragma unroll
        for (int j = 0; j < 8; ++j) acc[i][j] = 0.f;

    for (int k0 = 0; k0 < Kc; k0 += 16) {
#pragma unroll
        for (int it = 0; it < 2; ++it) {
            int f = tid + it * 128;
            int m = f >> 2, q = f & 3;
            float4 av = *(const float4*)(A + (size_t)m * lda + kbase + k0 + q * 4);
            As[q * 4 + 0][m] = av.x; As[q * 4 + 1][m] = av.y;
            As[q * 4 + 2][m] = av.z; As[q * 4 + 3][m] = av.w;
        }
#pragma unroll
        for (int it = 0; it < 4; ++it) {
            int f = tid + it * 128;
            int k = f >> 5, n4 = f & 31;
            *(float4*)&Bs[k][n4 * 4] =
                *(const float4*)(B + (size_t)(kbase + k0 + k) * ldb + nl + n4 * 4);
        }
        __syncthreads();
#pragma unroll
        for (int kk = 0; kk < 16; ++kk) {
            float a[8], b[8];
            *(float4*)(a)     = *(const float4*)&As[kk][trow * 8];
            *(float4*)(a + 4) = *(const float4*)&As[kk][trow * 8 + 4];
            *(float4*)(b)     = *(const float4*)&Bs[kk][tcol * 8];
            *(float4*)(b + 4) = *(const float4*)&Bs[kk][tcol * 8 + 4];
#pragma unroll
            for (int i = 0; i < 8; ++i)
#pragma unroll
                for (int j = 0; j < 8; ++j) acc[i][j] += a[i] * b[j];
        }
        __syncthreads();
    }

    float* Cz = part + (size_t)blockIdx.z * strideCz;
    int m0 = trow * 8;
    int n0g = bx * 128 + tcol * 8;
#pragma unroll
    for (int i = 0; i < 8; ++i) {
        float* crow = Cz + (size_t)(m0 + i) * ldc + n0g;
        *(float4*)(crow)     = make_float4(acc[i][0], acc[i][1], acc[i][2], acc[i][3]);
        *(float4*)(crow + 4) = make_float4(acc[i][4], acc[i][5], acc[i][6], acc[i][7]);
    }
}

// split-K reduce. mode 0: plain. 1: +bias. 2: vctx epilogue (builds Xc/Xv/Xn).
__global__ void k_reduce(const float* __restrict__ part, float* __restrict__ C,
                         int total, int splitk, const float* __restrict__ bias,
                         int mode, const float* __restrict__ v) {
    int idx = blockIdx.x * 256 + threadIdx.x;
    if (idx >= total) return;
    float s = 0.f;
    for (int z = 0; z < splitk; ++z) s += part[(size_t)z * total + idx];
    if (mode == 2) {
        int m = idx >> 10, d = idx & 1023;
        float a = v[idx];
        g_Xc[(size_t)m * 3072 + d] = s;
        float* xv = g_Xv + (size_t)m * 3072;
        xv[d] = a; xv[1024 + d] = s; xv[2048 + d] = a * s;
        float* xn = g_Xn + (size_t)m * 2048;
        xn[d] = a; xn[1024 + d] = s;
    } else {
        if (mode == 1) s += bias[idx & 1023];
        C[idx] = s;
    }
}

// ---------------- fused attention: score + masked softmax + ctx aggregation ----------
// grid (64, 2), 256 thr. y=0: row i (sbj, Qs2); y=1: col j (obj, Qo2).
// Writes ctx into Xc cols 1024+ (row) / 2048+ (col).
__global__ void __launch_bounds__(256) k_attn(const int* __restrict__ conn) {
    __shared__ int ke[64];
    __shared__ float sd[64];
    __shared__ float sinv;
    int tid = threadIdx.x;
    int i = blockIdx.x;
    bool rowdir = (blockIdx.y == 0);
    const float* q = g_QQ2 + (size_t)i * 2048 + (rowdir ? 0 : 1024);

    if (tid < 64)
        ke[tid] = rowdir ? conn[i * 64 + tid] : conn[tid * 64 + i];
    __syncthreads();

    // per-edge dots: warp w handles jj = w, w+8, ...
    int w = tid >> 5, lane = tid & 31;
    for (int jj = w; jj < 64; jj += 8) {
        int k = ke[jj];
        float dot = 0.f;
        if (k >= 0) {
            const float* r = g_relj + (size_t)k * Dm;
#pragma unroll
            for (int d = 0; d < 32; ++d) dot += q[lane + d * 32] * r[lane + d * 32];
#pragma unroll
            for (int off = 16; off; off >>= 1)
                dot += __shfl_down_sync(0xffffffffu, dot, off);
        }
        if (lane == 0) sd[jj] = (k >= 0) ? dot * (1.f / 32.f) : -1e30f;
    }
    __syncthreads();

    if (tid == 0) {
        float m = -1e30f;
        for (int j = 0; j < 64; ++j)
            if (ke[j] >= 0) m = fmaxf(m, sd[j]);
        float sum = 0.f;
        for (int j = 0; j < 64; ++j) {
            float e = (ke[j] >= 0) ? expf(sd[j] - m) : 0.f;
            sd[j] = e; sum += e;
        }
        sinv = 1.f / sum;
    }
    __syncthreads();

    float inv = sinv;
    float* dst = g_Xc + (size_t)i * 3072 + (rowdir ? 1024 : 2048);
#pragma unroll
    for (int dd = 0; dd < 4; ++dd) {
        int d = tid + dd * 256;
        float acc = 0.f;
        for (int j = 0; j < 64; ++j) {
            int k = ke[j];
            if (k >= 0) acc += (sd[j] * inv) * g_relj[(size_t)k * Dm + d];
        }
        dst[d] = acc;
    }
}

// ---------------- host side ----------------
static float* getsym(const void* s) {
    void* p = nullptr;
    cudaGetSymbolAddress(&p, s);
    return (float*)p;
}

extern "C" void kernel_launch(void* const* d_in, const int* in_sizes, int n_in,
                              void* d_out, int out_size) {
    (void)in_sizes; (void)n_in; (void)out_size;
    const float* v        = (const float*)d_in[0];
    const float* rel      = (const float*)d_in[1];
    const int*   conn     = (const int*)d_in[2];
    const int*   eidx     = (const int*)d_in[4];
    const float* W_sub    = (const float*)d_in[5];
    const float* W_obj    = (const float*)d_in[6];
    const float* W_r2s    = (const float*)d_in[7];
    const float* W_r2o    = (const float*)d_in[8];
    const float* W_joint  = (const float*)d_in[9];
    const float* W_ctx    = (const float*)d_in[10];
    const float* W_relup  = (const float*)d_in[11];
    const float* W_reljnt = (const float*)d_in[12];
    const float* W_relctx = (const float*)d_in[13];
    const float* W_node   = (const float*)d_in[14];
    const float* b_node   = (const float*)d_in[15];
    const float* W_factor = (const float*)d_in[16];

    float* out_f   = (float*)d_out;
    float* rel_out = out_f;
    float* v_out   = out_f + (size_t)Ne * Dm;

    float* Xv   = getsym(g_Xv);
    float* vj   = getsym(g_vj);
    float* SOQQ = getsym(g_SOQQ);
    float* QQ2  = getsym(g_QQ2);
    float* Xr   = getsym(g_Xr);
    float* rj   = getsym(g_rj);
    float* relj = getsym(g_relj);
    float* XrcB = getsym(g_Xrc2);
    float* Xc   = getsym(g_Xc);
    float* Xn   = getsym(g_Xn);
    float* part = getsym(g_part);
    float* WjA  = getsym(g_WjA);
    float* WjB  = getsym(g_WjB);
    float* WrA  = getsym(g_WrA);
    float* WrB  = getsym(g_WrB);
    float* Wr3  = getsym(g_Wr3);
    float* Wrc  = getsym(g_Wrc);
    float* Wf   = getsym(g_Wf);
    float* xrc[2] = {XrcB, XrcB + (size_t)Ne * 2048};

    k_setup<<<512, 256>>>(v, rel, eidx, xrc[0]);
    k_wcomb<<<4096, 256>>>(W_joint, W_reljnt, W_relup, W_relctx, W_factor);

    for (int t = 0; t < 2; ++t) {
        int Kx = (t == 0) ? 2048 : 3072;        // folded-K for vj/rj
        const float* Wj = (t == 0) ? WjA : WjB;
        const float* Wr = (t == 0) ? WrA : WrB;

        // vj = Xv @ Wj^T   (M=64, split-K 16, FFMA)
        k_gemm<<<dim3(8, 1, 16), 128>>>(Xv, Kx, Wj, Wj, Wj, Wj,
                                        Kx, Kx, part, 1024, 65536, Kx / 16);
        k_reduce<<<256, 256>>>(part, vj, 65536, 16, nullptr, 0, nullptr);

        // rj = Xr @ Wr^T  (tensor, folded K, rounded output)
        k_tgemm<3><<<dim3(16, 8), 256>>>(Xr, Kx, Wr, Kx, rj, Kx,
                                         nullptr, nullptr, 0);

        // node batch: SOQQ = vj @ [Ws | Wo | W_sub | W_obj]^T  (N=4096, split-K 8)
        k_gemm<<<dim3(32, 1, 8), 128>>>(vj, 1024, W_relup, W_relup + 1024, W_sub, W_obj,
                                        3072, 1024, part, 4096, 262144, 128);
        k_reduce<<<1024, 256>>>(part, SOQQ, 262144, 8, nullptr, 0, nullptr);

        // relj = S[src] + O[dst] + rj @ Wr3^T  (tensor, K=1024, epi -> xrc[t] 2nd half)
        k_tgemm<1><<<dim3(16, 8), 256>>>(rj, 1024, Wr3, 1024, relj, 1024,
                                         xrc[t], nullptr, 0);

        // QQ2 = [Qs @ W_r2s | Qo @ W_r2o]  (NN, N=2048, split-K 8)
        k_gemmNN<<<dim3(16, 1, 8), 128>>>(SOQQ + 2048, SOQQ + 3072, 4096,
                                          W_r2s, W_r2o, 1024,
                                          part, 2048, 131072, 128);
        k_reduce<<<512, 256>>>(part, QQ2, 131072, 8, nullptr, 0, nullptr);

        // fused score + softmax + ctx (writes Xc cols 1024+/2048+)
        k_attn<<<dim3(64, 2), 256>>>(conn);

        // vctx = Xc @ W_ctx^T  (M=64, K=3072, split-K 16; reduce builds Xc/Xv/Xn)
        k_gemm<<<dim3(8, 1, 16), 128>>>(Xc, 3072, W_ctx, W_ctx, W_ctx, W_ctx,
                                        3072, 3072, part, 1024, 65536, 192);
        k_reduce<<<256, 256>>>(part, nullptr, 65536, 16, nullptr, 2, v);

        // relctx = xrc[t] @ Wrc^T  (tensor K=2048; epi -> xrc[t^1] (+Xr) or final)
        k_tgemm<2><<<dim3(16, 8), 256>>>(xrc[t], 2048, Wrc, 2048, nullptr, 2048,
                                         xrc[t ^ 1], rel, (t == 0) ? 1 : 2);
    }

    // rel_out = [rel, relctx] @ Wf^T  (tensor K=2048)
    k_tgemm<0><<<dim3(16, 8), 256>>>(xrc[0], 2048, Wf, 2048, rel_out, 2048,
                                     nullptr, nullptr, 0);

    // v_out = Xn @ W_node^T + b_node
    k_gemm<<<dim3(8, 1, 16), 128>>>(Xn, 2048, W_node, W_node, W_node, W_node,
                                    2048, 2048, part, 1024, 65536, 128);
    k_reduce<<<256, 256>>>(part, v_out, 65536, 16, b_node, 1, nullptr);
}

// round 9
// speedup vs baseline: 3.2888x; 1.0021x over previous
#include <cuda_runtime.h>
#include <cstdint>

#define Dm 1024
#define Nn 64
#define Ne 1024

// ---------------- scratch (device globals; no allocations allowed) ----------------
__device__ float g_Xv[Nn * 3 * Dm];
__device__ float g_vj[Nn * Dm];
__device__ float g_SOQQ[Nn * 4 * Dm];    // [S | O | Qs | Qo], ldc 4096
__device__ float g_QQ2[Nn * 2 * Dm];     // [Qs2 | Qo2], ldc 2048
__device__ float g_Xr[Ne * 3 * Dm];      // tf32-rounded A of rj gemm
__device__ float g_rj[Ne * Dm];          // tf32-rounded
__device__ float g_relj[Ne * Dm];        // full f32
__device__ float g_Xrc2[2 * Ne * 2 * Dm];
__device__ float g_Xc[Nn * 3 * Dm];
__device__ float g_Xn[Nn * 2 * Dm];
__device__ float g_part[8 * Nn * 4 * Dm];
__device__ float g_WjA[Dm * 2048];
__device__ float g_WjB[Dm * 3072];
__device__ float g_WrA[Dm * 2048];
__device__ float g_WrB[Dm * 3072];
__device__ float g_Wr3[Dm * Dm];
__device__ float g_Wrc[Dm * 2048];
__device__ float g_Wf[Dm * 2048];
__device__ int g_src[Ne];
__device__ int g_dst[Ne];

__device__ __forceinline__ uint32_t f2tf32(float x) {
    uint32_t u;
    asm("cvt.rna.tf32.f32 %0, %1;" : "=r"(u) : "f"(x));
    return u;
}
__device__ __forceinline__ float rtf(float x) { return __uint_as_float(f2tf32(x)); }

__device__ __forceinline__ uint32_t smem_u32(const void* p) {
    uint32_t r;
    asm("{ .reg .u64 t; cvta.to.shared.u64 t, %1; cvt.u32.u64 %0, t; }" : "=r"(r) : "l"(p));
    return r;
}

// ---------------- init: weight folding + setup (merged) ----------------
__global__ void k_init(const float* __restrict__ Wj, const float* __restrict__ Wr,
                       const float* __restrict__ Wrelup, const float* __restrict__ Wrelctx,
                       const float* __restrict__ Wfactor,
                       const float* __restrict__ v, const float* __restrict__ rel,
                       const int* __restrict__ eidx, float* __restrict__ xrcA) {
    int idx = blockIdx.x * 256 + threadIdx.x;
    if (idx < Dm * Dm) {
        int o = idx >> 10, d = idx & 1023;
        {
            const float* r = Wj + (size_t)o * 4096;
            float w1 = r[d], w2 = r[1024 + d], w3 = r[2048 + d], w4 = r[3072 + d];
            g_WjA[(size_t)o * 2048 + d] = w1 + w2;
            g_WjA[(size_t)o * 2048 + 1024 + d] = w3;
            g_WjB[(size_t)o * 3072 + d] = w1 - w4;
            g_WjB[(size_t)o * 3072 + 1024 + d] = w2 + w4;
            g_WjB[(size_t)o * 3072 + 2048 + d] = w3;
        }
        {
            const float* r = Wr + (size_t)o * 4096;
            float w1 = r[d], w2 = r[1024 + d], w3 = r[2048 + d], w4 = r[3072 + d];
            g_WrA[(size_t)o * 2048 + d] = rtf(w1 + w2);
            g_WrA[(size_t)o * 2048 + 1024 + d] = rtf(w3);
            g_WrB[(size_t)o * 3072 + d] = rtf(w1 + w4);
            g_WrB[(size_t)o * 3072 + 1024 + d] = rtf(w2 - w4);
            g_WrB[(size_t)o * 3072 + 2048 + d] = rtf(w3);
        }
        g_Wr3[(size_t)o * 1024 + d] = rtf(Wrelup[(size_t)o * 3072 + 2048 + d]);
        g_Wrc[(size_t)o * 2048 + d] = rtf(Wrelctx[(size_t)o * 2048 + d]);
        g_Wrc[(size_t)o * 2048 + 1024 + d] = rtf(Wrelctx[(size_t)o * 2048 + 1024 + d]);
        g_Wf[(size_t)o * 2048 + d] = rtf(Wfactor[(size_t)o * 2048 + d]);
        g_Wf[(size_t)o * 2048 + 1024 + d] = rtf(Wfactor[(size_t)o * 2048 + 1024 + d]);
    }
    int stride = gridDim.x * 256;
    for (int t = idx; t < Ne * Dm; t += stride) {
        int e = t >> 10, d = t & 1023;
        float r = rel[t];
        float* xr = g_Xr + (size_t)e * 2048;
        xr[d] = rtf(r); xr[1024 + d] = rtf(r * r);
        xrcA[(size_t)e * 2048 + d] = rtf(r);
    }
    for (int t = idx; t < Nn * Dm; t += stride) {
        int i = t >> 10, d = t & 1023;
        float a = v[t];
        float* xv = g_Xv + (size_t)i * 2048;
        xv[d] = a; xv[1024 + d] = a * a;
        g_Xc[(size_t)i * 3072 + d] = a;
    }
    for (int t = idx; t < Ne; t += stride) {
        int e = eidx[t];
        g_src[t] = e >> 6;
        g_dst[t] = e & 63;
    }
}

// ======================= tf32 tensor-core NT GEMM (cp.async, BK=32, 3-stage) ======
// C[M,1024] = A[M,K] * B[1024,K]^T, BM=128 BN=64 BK=32, 256 thr, 8 warps 32x32.
// Dynamic smem: As TS*128*36 + Bs TS*64*36 floats = 82944 B.
// Inputs PRE-ROUNDED to tf32.
// MODE 0: write C (f32).  MODE 3: write C rounded.
// MODE 1: C += SOQQ[src]+SOQQ[dst+1024] (f32); xrc 2nd half rounded.
// MODE 2: no C; flag==1 -> xrc relctx + Xr=[rel,ctx,rel*ctx] rounded (ld 3072);
//         flag==2 -> final xrc=[rel, relctx] rounded.
#define TS 3
#define BK 32
#define APAD 36
#define A_STG (128 * APAD)
#define B_STG (64 * APAD)
#define SMEM_BYTES ((TS * A_STG + TS * B_STG) * 4)

template <int MODE>
__global__ void __launch_bounds__(256) k_tgemm(
    const float* __restrict__ A, int lda,
    const float* __restrict__ B, int ldb,
    float* __restrict__ C, int K,
    float* __restrict__ xrc_w, const float* __restrict__ rel, int flag) {
    extern __shared__ float smem[];
    float* As = smem;                  // [TS][128][APAD]
    float* Bs = smem + TS * A_STG;     // [TS][64][APAD]

    int tid = threadIdx.x;
    int lane = tid & 31;
    int w = tid >> 5;
    int wm = (w & 3) * 32;
    int wn = (w >> 2) * 32;
    int gr = lane >> 2;
    int gc = lane & 3;

    // cp.async mapping: A 128 rows x 128B -> 4x16B/thread (row=t>>1, half=(t&1)*16)
    //                   B 64 rows x 128B  -> 2x16B/thread (row=t>>2, q=(t&3)*8)
    const float* Ag = A + (size_t)(blockIdx.y * 128 + (tid >> 1)) * lda + (tid & 1) * 16;
    const float* Bg = B + (size_t)(blockIdx.x * 64 + (tid >> 2)) * ldb + (tid & 3) * 8;
    uint32_t a_dst = smem_u32(&As[(tid >> 1) * APAD + (tid & 1) * 16]);
    uint32_t b_dst = smem_u32(&Bs[(tid >> 2) * APAD + (tid & 3) * 8]);

    int niter = K >> 5;

#define ISSUE_STAGE(s, k0)                                                                   \
    do {                                                                                     \
        uint32_t ad = a_dst + (uint32_t)(s) * (A_STG * 4);                                   \
        const float* ap = Ag + (k0);                                                         \
        asm volatile("cp.async.cg.shared.global [%0], [%1], 16;" :: "r"(ad), "l"(ap));       \
        asm volatile("cp.async.cg.shared.global [%0], [%1], 16;" :: "r"(ad + 16), "l"(ap + 4)); \
        asm volatile("cp.async.cg.shared.global [%0], [%1], 16;" :: "r"(ad + 32), "l"(ap + 8)); \
        asm volatile("cp.async.cg.shared.global [%0], [%1], 16;" :: "r"(ad + 48), "l"(ap + 12)); \
        uint32_t bd = b_dst + (uint32_t)(s) * (B_STG * 4);                                   \
        const float* bp = Bg + (k0);                                                         \
        asm volatile("cp.async.cg.shared.global [%0], [%1], 16;" :: "r"(bd), "l"(bp));       \
        asm volatile("cp.async.cg.shared.global [%0], [%1], 16;" :: "r"(bd + 16), "l"(bp + 4)); \
    } while (0)

    ISSUE_STAGE(0, 0);
    asm volatile("cp.async.commit_group;");
    ISSUE_STAGE(1, BK);
    asm volatile("cp.async.commit_group;");

    float c[2][4][4];
#pragma unroll
    for (int mt = 0; mt < 2; ++mt)
#pragma unroll
        for (int nt = 0; nt < 4; ++nt)
#pragma unroll
            for (int q = 0; q < 4; ++q) c[mt][nt][q] = 0.f;

    const uint32_t* Asu = reinterpret_cast<const uint32_t*>(As);
    const uint32_t* Bsu = reinterpret_cast<const uint32_t*>(Bs);

    int s = 0;
    for (int i = 0; i < niter; ++i) {
        asm volatile("cp.async.wait_group 1;" ::: "memory");
        __syncthreads();
        {
            int nx = i + 2;
            if (nx < niter) {
                int sn = s + 2; if (sn >= TS) sn -= TS;
                ISSUE_STAGE(sn, nx * BK);
            }
            asm volatile("cp.async.commit_group;");
        }
        int base_a = s * A_STG;
        int base_b = s * B_STG;
#pragma unroll
        for (int half = 0; half < 2; ++half) {
            // two k-groups per half; prefetch both, then 16 MMAs
            uint32_t a[2][2][4], b[2][4][2];
#pragma unroll
            for (int ks = 0; ks < 2; ++ks) {
                int kb = half * 16 + ks * 8 + gc;
#pragma unroll
                for (int mt = 0; mt < 2; ++mt) {
                    int m0 = wm + mt * 16 + gr;
                    a[ks][mt][0] = Asu[base_a + m0 * APAD + kb];
                    a[ks][mt][1] = Asu[base_a + (m0 + 8) * APAD + kb];
                    a[ks][mt][2] = Asu[base_a + m0 * APAD + kb + 4];
                    a[ks][mt][3] = Asu[base_a + (m0 + 8) * APAD + kb + 4];
                }
#pragma unroll
                for (int nt = 0; nt < 4; ++nt) {
                    int n0 = wn + nt * 8 + gr;
                    b[ks][nt][0] = Bsu[base_b + n0 * APAD + kb];
                    b[ks][nt][1] = Bsu[base_b + n0 * APAD + kb + 4];
                }
            }
#pragma unroll
            for (int ks = 0; ks < 2; ++ks)
#pragma unroll
                for (int mt = 0; mt < 2; ++mt)
#pragma unroll
                    for (int nt = 0; nt < 4; ++nt) {
                        asm volatile(
                            "mma.sync.aligned.m16n8k8.row.col.f32.tf32.tf32.f32 "
                            "{%0,%1,%2,%3}, {%4,%5,%6,%7}, {%8,%9}, {%0,%1,%2,%3};"
                            : "+f"(c[mt][nt][0]), "+f"(c[mt][nt][1]),
                              "+f"(c[mt][nt][2]), "+f"(c[mt][nt][3])
                            : "r"(a[ks][mt][0]), "r"(a[ks][mt][1]),
                              "r"(a[ks][mt][2]), "r"(a[ks][mt][3]),
                              "r"(b[ks][nt][0]), "r"(b[ks][nt][1]));
                    }
        }
        if (++s >= TS) s -= TS;
    }
#undef ISSUE_STAGE

    int mbase = blockIdx.y * 128 + wm;
    int nbase = blockIdx.x * 64 + wn;
#pragma unroll
    for (int mt = 0; mt < 2; ++mt) {
#pragma unroll
        for (int half = 0; half < 2; ++half) {
            int row = mbase + mt * 16 + gr + half * 8;
#pragma unroll
            for (int nt = 0; nt < 4; ++nt) {
                int col = nbase + nt * 8 + 2 * gc;
                float vx = c[mt][nt][half * 2 + 0];
                float vy = c[mt][nt][half * 2 + 1];
                if (MODE == 0) {
                    *(float2*)(C + (size_t)row * 1024 + col) = make_float2(vx, vy);
                } else if (MODE == 3) {
                    *(float2*)(C + (size_t)row * 1024 + col) = make_float2(rtf(vx), rtf(vy));
                } else if (MODE == 1) {
                    const float* sp = g_SOQQ + (size_t)g_src[row] * 4096 + col;
                    const float* op = g_SOQQ + (size_t)g_dst[row] * 4096 + 1024 + col;
                    vx += sp[0] + op[0];
                    vy += sp[1] + op[1];
                    *(float2*)(C + (size_t)row * 1024 + col) = make_float2(vx, vy);
                    *(float2*)(xrc_w + (size_t)row * 2048 + 1024 + col) =
                        make_float2(rtf(vx), rtf(vy));
                } else {  // MODE 2
                    float2 rv = *(const float2*)(rel + (size_t)row * 1024 + col);
                    if (flag == 1) {
                        *(float2*)(xrc_w + (size_t)row * 2048 + col) =
                            make_float2(rtf(vx), rtf(vy));
                        float* xr = g_Xr + (size_t)row * 3072;
                        *(float2*)(xr + col)        = make_float2(rtf(rv.x), rtf(rv.y));
                        *(float2*)(xr + 1024 + col) = make_float2(rtf(vx), rtf(vy));
                        *(float2*)(xr + 2048 + col) =
                            make_float2(rtf(rv.x * vx), rtf(rv.y * vy));
                    } else {
                        *(float2*)(xrc_w + (size_t)row * 2048 + col) =
                            make_float2(rtf(rv.x), rtf(rv.y));
                        *(float2*)(xrc_w + (size_t)row * 2048 + 1024 + col) =
                            make_float2(rtf(vx), rtf(vy));
                    }
                }
            }
        }
    }
}

// ---------------- FFMA NT GEMM, M=64, split-K, 4-region B select ----------------
__global__ void __launch_bounds__(128) k_gemm(
    const float* __restrict__ A, int lda,
    const float* __restrict__ B0, const float* __restrict__ B1,
    const float* __restrict__ B2, const float* __restrict__ B3,
    int ldb01, int ldb23,
    float* __restrict__ part, int ldc, size_t strideCz, int Kc) {
    __shared__ float As[16][64];
    __shared__ float Bs[16][128];
    int tid = threadIdx.x;
    int trow = tid >> 4;
    int tcol = tid & 15;
    int bx = blockIdx.x;
    int region = bx >> 3;
    const float* Bp = (region == 0) ? B0 : (region == 1) ? B1 : (region == 2) ? B2 : B3;
    int ldb = (region < 2) ? ldb01 : ldb23;
    const float* Ab = A + (size_t)blockIdx.z * Kc;
    const float* Bb = Bp + (size_t)((bx & 7) * 128) * ldb + (size_t)blockIdx.z * Kc;

    float acc[8][8];
#pragma unroll
    for (int i = 0; i < 8; ++i)
#pragma unroll
        for (int j = 0; j < 8; ++j) acc[i][j] = 0.f;

    for (int k0 = 0; k0 < Kc; k0 += 16) {
#pragma unroll
        for (int it = 0; it < 2; ++it) {
            int f = tid + it * 128;
            int r = f >> 2, q = f & 3;
            float4 vv = *(const float4*)(Ab + (size_t)r * lda + k0 + q * 4);
            As[q * 4 + 0][r] = vv.x; As[q * 4 + 1][r] = vv.y;
            As[q * 4 + 2][r] = vv.z; As[q * 4 + 3][r] = vv.w;
        }
#pragma unroll
        for (int it = 0; it < 4; ++it) {
            int f = tid + it * 128;
            int r = f >> 2, q = f & 3;
            float4 vv = *(const float4*)(Bb + (size_t)r * ldb + k0 + q * 4);
            Bs[q * 4 + 0][r] = vv.x; Bs[q * 4 + 1][r] = vv.y;
            Bs[q * 4 + 2][r] = vv.z; Bs[q * 4 + 3][r] = vv.w;
        }
        __syncthreads();
#pragma unroll
        for (int kk = 0; kk < 16; ++kk) {
            float a[8], b[8];
            *(float4*)(a)     = *(const float4*)&As[kk][trow * 8];
            *(float4*)(a + 4) = *(const float4*)&As[kk][trow * 8 + 4];
            *(float4*)(b)     = *(const float4*)&Bs[kk][tcol * 8];
            *(float4*)(b + 4) = *(const float4*)&Bs[kk][tcol * 8 + 4];
#pragma unroll
            for (int i = 0; i < 8; ++i)
#pragma unroll
                for (int j = 0; j < 8; ++j) acc[i][j] += a[i] * b[j];
        }
        __syncthreads();
    }

    float* Cz = part + (size_t)blockIdx.z * strideCz;
    int m0 = trow * 8;
    int n0g = bx * 128 + tcol * 8;
#pragma unroll
    for (int i = 0; i < 8; ++i) {
        float* crow = Cz + (size_t)(m0 + i) * ldc + n0g;
        *(float4*)(crow)     = make_float4(acc[i][0], acc[i][1], acc[i][2], acc[i][3]);
        *(float4*)(crow + 4) = make_float4(acc[i][4], acc[i][5], acc[i][6], acc[i][7]);
    }
}

// ---------------- FFMA NN GEMM, M=64, split-K, 2-region A/B select ----------------
__global__ void __launch_bounds__(128) k_gemmNN(
    const float* __restrict__ A0, const float* __restrict__ A1, int lda,
    const float* __restrict__ B0, const float* __restrict__ B1, int ldb,
    float* __restrict__ part, int ldc, size_t strideCz, int Kc) {
    __shared__ float As[16][64];
    __shared__ float Bs[16][128];
    int tid = threadIdx.x;
    int trow = tid >> 4;
    int tcol = tid & 15;
    int bx = blockIdx.x;
    int region = bx >> 3;
    const float* A = region ? A1 : A0;
    const float* B = region ? B1 : B0;
    int nl = (bx & 7) * 128;
    int kbase = blockIdx.z * Kc;

    float acc[8][8];
#pragma unroll
    for (int i = 0; i < 8; ++i)
#pragma unroll
        for (int j = 0; j < 8; ++j) acc[i][j] = 0.f;

    for (int k0 = 0; k0 < Kc; k0 += 16) {
#pragma unroll
        for (int it = 0; it < 2; ++it) {
            int f = tid + it * 128;
            int m = f >> 2, q = f & 3;
            float4 av = *(const float4*)(A + (size_t)m * lda + kbase + k0 + q * 4);
            As[q * 4 + 0][m] = av.x; As[q * 4 + 1][m] = av.y;
            As[q * 4 + 2][m] = av.z; As[q * 4 + 3][m] = av.w;
        }
#pragma unroll
        for (int it = 0; it < 4; ++it) {
            int f = tid + it * 128;
            int k = f >> 5, n4 = f & 31;
            *(float4*)&Bs[k][n4 * 4] =
                *(const float4*)(B + (size_t)(kbase + k0 + k) * ldb + nl + n4 * 4);
        }
        __syncthreads();
#pragma unroll
        for (int kk = 0; kk < 16; ++kk) {
            float a[8], b[8];
            *(float4*)(a)     = *(const float4*)&As[kk][trow * 8];
            *(float4*)(a + 4) = *(const float4*)&As[kk][trow * 8 + 4];
            *(float4*)(b)     = *(const float4*)&Bs[kk][tcol * 8];
            *(float4*)(b + 4) = *(const float4*)&Bs[kk][tcol * 8 + 4];
#pragma unroll
            for (int i = 0; i < 8; ++i)
#pragma unroll
                for (int j = 0; j < 8; ++j) acc[i][j] += a[i] * b[j];
        }
        __syncthreads();
    }

    float* Cz = part + (size_t)blockIdx.z * strideCz;
    int m0 = trow * 8;
    int n0g = bx * 128 + tcol * 8;
#pragma unroll
    for (int i = 0; i < 8; ++i) {
        float* crow = Cz + (size_t)(m0 + i) * ldc + n0g;
        *(float4*)(crow)     = make_float4(acc[i][0], acc[i][1], acc[i][2], acc[i][3]);
        *(float4*)(crow + 4) = make_float4(acc[i][4], acc[i][5], acc[i][6], acc[i][7]);
    }
}

// split-K reduce. mode 0: plain. 1: +bias. 2: vctx epilogue (builds Xc/Xv/Xn).
__global__ void k_reduce(const float* __restrict__ part, float* __restrict__ C,
                         int total, int splitk, const float* __restrict__ bias,
                         int mode, const float* __restrict__ v) {
    int idx = blockIdx.x * 256 + threadIdx.x;
    if (idx >= total) return;
    float s = 0.f;
    for (int z = 0; z < splitk; ++z) s += part[(size_t)z * total + idx];
    if (mode == 2) {
        int m = idx >> 10, d = idx & 1023;
        float a = v[idx];
        g_Xc[(size_t)m * 3072 + d] = s;
        float* xv = g_Xv + (size_t)m * 3072;
        xv[d] = a; xv[1024 + d] = s; xv[2048 + d] = a * s;
        float* xn = g_Xn + (size_t)m * 2048;
        xn[d] = a; xn[1024 + d] = s;
    } else {
        if (mode == 1) s += bias[idx & 1023];
        C[idx] = s;
    }
}

// ---------------- fused attention: score + masked softmax + ctx aggregation ----------
__global__ void __launch_bounds__(256) k_attn(const int* __restrict__ conn) {
    __shared__ int ke[64];
    __shared__ float sd[64];
    __shared__ float sinv;
    int tid = threadIdx.x;
    int i = blockIdx.x;
    bool rowdir = (blockIdx.y == 0);
    const float* q = g_QQ2 + (size_t)i * 2048 + (rowdir ? 0 : 1024);

    if (tid < 64)
        ke[tid] = rowdir ? conn[i * 64 + tid] : conn[tid * 64 + i];
    __syncthreads();

    int w = tid >> 5, lane = tid & 31;
    for (int jj = w; jj < 64; jj += 8) {
        int k = ke[jj];
        float dot = 0.f;
        if (k >= 0) {
            const float* r = g_relj + (size_t)k * Dm;
#pragma unroll
            for (int d = 0; d < 32; ++d) dot += q[lane + d * 32] * r[lane + d * 32];
#pragma unroll
            for (int off = 16; off; off >>= 1)
                dot += __shfl_down_sync(0xffffffffu, dot, off);
        }
        if (lane == 0) sd[jj] = (k >= 0) ? dot * (1.f / 32.f) : -1e30f;
    }
    __syncthreads();

    if (tid == 0) {
        float m = -1e30f;
        for (int j = 0; j < 64; ++j)
            if (ke[j] >= 0) m = fmaxf(m, sd[j]);
        float sum = 0.f;
        for (int j = 0; j < 64; ++j) {
            float e = (ke[j] >= 0) ? expf(sd[j] - m) : 0.f;
            sd[j] = e; sum += e;
        }
        sinv = 1.f / sum;
    }
    __syncthreads();

    float inv = sinv;
    float* dst = g_Xc + (size_t)i * 3072 + (rowdir ? 1024 : 2048);
#pragma unroll
    for (int dd = 0; dd < 4; ++dd) {
        int d = tid + dd * 256;
        float acc = 0.f;
        for (int j = 0; j < 64; ++j) {
            int k = ke[j];
            if (k >= 0) acc += (sd[j] * inv) * g_relj[(size_t)k * Dm + d];
        }
        dst[d] = acc;
    }
}

// ---------------- host side ----------------
static float* getsym(const void* s) {
    void* p = nullptr;
    cudaGetSymbolAddress(&p, s);
    return (float*)p;
}

extern "C" void kernel_launch(void* const* d_in, const int* in_sizes, int n_in,
                              void* d_out, int out_size) {
    (void)in_sizes; (void)n_in; (void)out_size;
    const float* v        = (const float*)d_in[0];
    const float* rel      = (const float*)d_in[1];
    const int*   conn     = (const int*)d_in[2];
    const int*   eidx     = (const int*)d_in[4];
    const float* W_sub    = (const float*)d_in[5];
    const float* W_obj    = (const float*)d_in[6];
    const float* W_r2s    = (const float*)d_in[7];
    const float* W_r2o    = (const float*)d_in[8];
    const float* W_joint  = (const float*)d_in[9];
    const float* W_ctx    = (const float*)d_in[10];
    const float* W_relup  = (const float*)d_in[11];
    const float* W_reljnt = (const float*)d_in[12];
    const float* W_relctx = (const float*)d_in[13];
    const float* W_node   = (const float*)d_in[14];
    const float* b_node   = (const float*)d_in[15];
    const float* W_factor = (const float*)d_in[16];

    float* out_f   = (float*)d_out;
    float* rel_out = out_f;
    float* v_out   = out_f + (size_t)Ne * Dm;

    float* Xv   = getsym(g_Xv);
    float* vj   = getsym(g_vj);
    float* SOQQ = getsym(g_SOQQ);
    float* QQ2  = getsym(g_QQ2);
    float* Xr   = getsym(g_Xr);
    float* rj   = getsym(g_rj);
    float* relj = getsym(g_relj);
    float* XrcB = getsym(g_Xrc2);
    float* Xc   = getsym(g_Xc);
    float* Xn   = getsym(g_Xn);
    float* part = getsym(g_part);
    float* WjA  = getsym(g_WjA);
    float* WjB  = getsym(g_WjB);
    float* WrA  = getsym(g_WrA);
    float* WrB  = getsym(g_WrB);
    float* Wr3  = getsym(g_Wr3);
    float* Wrc  = getsym(g_Wrc);
    float* Wf   = getsym(g_Wf);
    float* xrc[2] = {XrcB, XrcB + (size_t)Ne * 2048};

    // opt-in to 81KB dynamic smem for each tgemm instantiation (idempotent host calls)
    cudaFuncSetAttribute(k_tgemm<0>, cudaFuncAttributeMaxDynamicSharedMemorySize, SMEM_BYTES);
    cudaFuncSetAttribute(k_tgemm<1>, cudaFuncAttributeMaxDynamicSharedMemorySize, SMEM_BYTES);
    cudaFuncSetAttribute(k_tgemm<2>, cudaFuncAttributeMaxDynamicSharedMemorySize, SMEM_BYTES);
    cudaFuncSetAttribute(k_tgemm<3>, cudaFuncAttributeMaxDynamicSharedMemorySize, SMEM_BYTES);

    k_init<<<4096, 256>>>(W_joint, W_reljnt, W_relup, W_relctx, W_factor,
                          v, rel, eidx, xrc[0]);

    for (int t = 0; t < 2; ++t) {
        int Kx = (t == 0) ? 2048 : 3072;
        const float* Wj = (t == 0) ? WjA : WjB;
        const float* Wr = (t == 0) ? WrA : WrB;

        // vj = Xv @ Wj^T   (M=64, split-K 16, FFMA)
        k_gemm<<<dim3(8, 1, 16), 128>>>(Xv, Kx, Wj, Wj, Wj, Wj,
                                        Kx, Kx, part, 1024, 65536, Kx / 16);
        k_reduce<<<256, 256>>>(part, vj, 65536, 16, nullptr, 0, nullptr);

        // rj = Xr @ Wr^T  (tensor, folded K, rounded output)
        k_tgemm<3><<<dim3(16, 8), 256, SMEM_BYTES>>>(Xr, Kx, Wr, Kx, rj, Kx,
                                                     nullptr, nullptr, 0);

        // node batch: SOQQ = vj @ [Ws | Wo | W_sub | W_obj]^T  (N=4096, split-K 8)
        k_gemm<<<dim3(32, 1, 8), 128>>>(vj, 1024, W_relup, W_relup + 1024, W_sub, W_obj,
                                        3072, 1024, part, 4096, 262144, 128);
        k_reduce<<<1024, 256>>>(part, SOQQ, 262144, 8, nullptr, 0, nullptr);

        // relj = S[src] + O[dst] + rj @ Wr3^T  (tensor, K=1024, epi -> xrc[t] 2nd half)
        k_tgemm<1><<<dim3(16, 8), 256, SMEM_BYTES>>>(rj, 1024, Wr3, 1024, relj, 1024,
                                                     xrc[t], nullptr, 0);

        // QQ2 = [Qs @ W_r2s | Qo @ W_r2o]  (NN, N=2048, split-K 8)
        k_gemmNN<<<dim3(16, 1, 8), 128>>>(SOQQ + 2048, SOQQ + 3072, 4096,
                                          W_r2s, W_r2o, 1024,
                                          part, 2048, 131072, 128);
        k_reduce<<<512, 256>>>(part, QQ2, 131072, 8, nullptr, 0, nullptr);

        // fused score + softmax + ctx (writes Xc cols 1024+/2048+)
        k_attn<<<dim3(64, 2), 256>>>(conn);

        // vctx = Xc @ W_ctx^T  (M=64, K=3072, split-K 16; reduce builds Xc/Xv/Xn)
        k_gemm<<<dim3(8, 1, 16), 128>>>(Xc, 3072, W_ctx, W_ctx, W_ctx, W_ctx,
                                        3072, 3072, part, 1024, 65536, 192);
        k_reduce<<<256, 256>>>(part, nullptr, 65536, 16, nullptr, 2, v);

        // relctx = xrc[t] @ Wrc^T  (tensor K=2048; epi -> xrc[t^1] (+Xr) or final)
        k_tgemm<2><<<dim3(16, 8), 256, SMEM_BYTES>>>(xrc[t], 2048, Wrc, 2048, nullptr, 2048,
                                                     xrc[t ^ 1], rel, (t == 0) ? 1 : 2);
    }

    // rel_out = [rel, relctx] @ Wf^T  (tensor K=2048)
    k_tgemm<0><<<dim3(16, 8), 256, SMEM_BYTES>>>(xrc[0], 2048, Wf, 2048, rel_out, 2048,
                                                 nullptr, nullptr, 0);

    // v_out = Xn @ W_node^T + b_node
    k_gemm<<<dim3(8, 1, 16), 128>>>(Xn, 2048, W_node, W_node, W_node, W_node,
                                    2048, 2048, part, 1024, 65536, 128);
    k_reduce<<<256, 256>>>(part, v_out, 65536, 16, b_node, 1, nullptr);
}